// round 3
// baseline (speedup 1.0000x reference)
#include <cuda_runtime.h>
#include <cuda_bf16.h>

typedef unsigned long long ull;

// Problem constants
#define BATCH 64
#define LSEQ  400
#define CIN   500
#define DMODEL 128
#define NHEAD 8
#define HDIM  16
#define MROWS (BATCH*LSEQ)          // 25600
#define LPAD  (LSEQ+4)              // 404
#define KCONV 2500                  // 5*500

// ---------------- scratch (static device globals; no allocation allowed) ---
__device__ float g_xpad[BATCH*LPAD*CIN + 64];
__device__ float g_pe[LSEQ*DMODEL];
__device__ float g_h [MROWS*DMODEL];
__device__ float g_ln[MROWS*DMODEL];
__device__ float g_tmp[MROWS*DMODEL];
__device__ float g_q [MROWS*DMODEL];
__device__ float g_k [MROWS*DMODEL];
__device__ float g_v [MROWS*DMODEL];
__device__ float g_att[MROWS*DMODEL];

// ---------------- f32x2 helpers (FFMA2: 2x fp32 throughput on sm_103a) -----
__device__ __forceinline__ ull pack2(float a){
    ull r; asm("mov.b64 %0, {%1, %1};" : "=l"(r) : "f"(a)); return r;
}
__device__ __forceinline__ void ffma2(ull& c, ull a, ull b){
    asm("fma.rn.f32x2 %0, %1, %2, %0;" : "+l"(c) : "l"(a), "l"(b));
}
__device__ __forceinline__ void mul2(ull& c, ull a){
    asm("mul.rn.f32x2 %0, %0, %1;" : "+l"(c) : "l"(a));
}

// FMA-pipe exp (avoids MUFU bottleneck: 0.5 MUFU/cyc/SM would cost ~600us here)
__device__ __forceinline__ float fexp(float x){
    x = fmaxf(x, -87.0f);
    float t = x * 1.4426950408889634f;   // x * log2(e)
    float fl = floorf(t);
    float f = t - fl;
    float p =       1.5403530e-4f;
    p = fmaf(p, f, 1.3333558e-3f);
    p = fmaf(p, f, 9.6181291e-3f);
    p = fmaf(p, f, 5.5504109e-2f);
    p = fmaf(p, f, 2.4022651e-1f);
    p = fmaf(p, f, 6.9314718e-1f);
    p = fmaf(p, f, 1.0f);
    int e = (int)fl;
    return p * __int_as_float((e + 127) << 23);
}

// ---------------- pad x into [B,404,500] (conv -> pure GEMM) ---------------
__global__ void __launch_bounds__(256) pad_kernel(const float* __restrict__ x){
    int idx = blockIdx.x*256 + threadIdx.x;
    if (idx >= BATCH*LPAD*CIN) return;
    int c = idx % CIN;
    int rest = idx / CIN;
    int lp = rest % LPAD;
    int b  = rest / LPAD;
    int l = lp - 2;
    g_xpad[idx] = (l >= 0 && l < LSEQ) ? x[(b*LSEQ + l)*CIN + c] : 0.f;
}

// ---------------- positional encoding table [400,128] ----------------------
__global__ void __launch_bounds__(256) pe_kernel(){
    int idx = blockIdx.x*256 + threadIdx.x;
    if (idx >= LSEQ*DMODEL) return;
    int l = idx / DMODEL;
    int d = idx % DMODEL;
    int j = d & ~1;
    float div = expf(-(float)j * (logf(10000.f)/(float)DMODEL));
    float ang = (float)l * div;
    g_pe[idx] = (d & 1) ? cosf(ang) : sinf(ang);
}

// ---------------- init conv as GEMM: M=25600, N=128, K=2500 ----------------
// BM=64, BN=128, BK=16, 128 threads, 8x8 register tile via FFMA2
__global__ void __launch_bounds__(128) conv_gemm_kernel(
    const float* __restrict__ Wf,      // [2500][128]
    const float* __restrict__ bias,    // [128]
    float* __restrict__ C)
{
    __shared__ float As[16*132];
    __shared__ float Ws[16*128];
    int t = threadIdx.x;
    int m0 = blockIdx.x * 64;
    int ty = t >> 4, tx = t & 15;

    ull c2[8][4];
    #pragma unroll
    for (int i=0;i<8;i++)
        #pragma unroll
        for (int j=0;j<4;j++) c2[i][j] = 0ull;

    // A-loader: per-thread fixed k-lane (kk) and 8 rows
    int kk = t & 15;
    int rr[8], rbase[8];
    #pragma unroll
    for (int e=0;e<8;e++){
        int r = (t >> 4) + e*8;           // 0..63
        rr[e] = r;
        int mrow = m0 + r;
        int b = mrow / LSEQ;
        int l = mrow - b*LSEQ;
        rbase[e] = (b*LPAD + l)*CIN;      // padded: flat offset == gk
    }

    for (int k0 = 0; k0 < KCONV; k0 += 16){
        int gk = k0 + kk;
        bool ok = gk < KCONV;
        #pragma unroll
        for (int e=0;e<8;e++)
            As[kk*132 + rr[e]] = ok ? g_xpad[rbase[e] + gk] : 0.f;
        #pragma unroll
        for (int qd=0; qd<4; qd++){
            int idx = t + qd*128;
            int wk_ = idx >> 5;
            int n4  = idx & 31;
            float4 wv = make_float4(0.f,0.f,0.f,0.f);
            if (k0 + wk_ < KCONV)
                wv = *(const float4*)&Wf[(k0+wk_)*DMODEL + n4*4];
            *(float4*)&Ws[wk_*128 + n4*4] = wv;
        }
        __syncthreads();
        #pragma unroll
        for (int k=0;k<16;k++){
            float a[8];
            *(float4*)&a[0] = *(const float4*)&As[k*132 + ty*8];
            *(float4*)&a[4] = *(const float4*)&As[k*132 + ty*8 + 4];
            const ull* wp = (const ull*)&Ws[k*128 + tx*8];
            ull w2[4];
            #pragma unroll
            for (int j=0;j<4;j++) w2[j] = wp[j];
            #pragma unroll
            for (int i=0;i<8;i++){
                ull a2 = pack2(a[i]);
                #pragma unroll
                for (int j=0;j<4;j++) ffma2(c2[i][j], a2, w2[j]);
            }
        }
        __syncthreads();
    }

    int col0 = tx*8;
    float bv[8];
    *(float4*)&bv[0] = *(const float4*)&bias[col0];
    *(float4*)&bv[4] = *(const float4*)&bias[col0+4];
    #pragma unroll
    for (int i=0;i<8;i++){
        int row = m0 + ty*8 + i;
        int l = row % LSEQ;
        float pv[8];
        *(float4*)&pv[0] = *(const float4*)&g_pe[l*DMODEL+col0];
        *(float4*)&pv[4] = *(const float4*)&g_pe[l*DMODEL+col0+4];
        float v[8];
        #pragma unroll
        for (int j=0;j<4;j++){ float2 f = *(float2*)&c2[i][j]; v[2*j]=f.x; v[2*j+1]=f.y; }
        #pragma unroll
        for (int jj=0;jj<8;jj++) v[jj] += bv[jj] + pv[jj];
        *(float4*)&C[row*DMODEL+col0]   = make_float4(v[0],v[1],v[2],v[3]);
        *(float4*)&C[row*DMODEL+col0+4] = make_float4(v[4],v[5],v[6],v[7]);
    }
}

// ---------------- generic 128x128 GEMM: C = act(A@W + b) [+ res] -----------
__global__ void __launch_bounds__(128) gemm_kernel(
    const float* __restrict__ A, const float* __restrict__ W,
    const float* __restrict__ bias, const float* __restrict__ res,
    float* __restrict__ C, int relu_flag, int res_flag)
{
    __shared__ float As[16*132];
    __shared__ float Ws[16*128];
    int t = threadIdx.x;
    int m0 = blockIdx.x * 64;
    int ty = t >> 4, tx = t & 15;

    ull c2[8][4];
    #pragma unroll
    for (int i=0;i<8;i++)
        #pragma unroll
        for (int j=0;j<4;j++) c2[i][j] = 0ull;

    int arow = t >> 1;          // 0..63
    int aq   = (t & 1) * 2;     // float4 index base {0,2}

    for (int k0=0; k0<DMODEL; k0+=16){
        #pragma unroll
        for (int q=0;q<2;q++){
            float4 av = *(const float4*)&A[(m0+arow)*DMODEL + k0 + (aq+q)*4];
            int kb = (aq+q)*4;
            As[(kb+0)*132+arow]=av.x; As[(kb+1)*132+arow]=av.y;
            As[(kb+2)*132+arow]=av.z; As[(kb+3)*132+arow]=av.w;
        }
        #pragma unroll
        for (int qd=0;qd<4;qd++){
            int idx = t + qd*128;
            int wk_ = idx >> 5;
            int n4  = idx & 31;
            *(float4*)&Ws[wk_*128+n4*4] = *(const float4*)&W[(k0+wk_)*DMODEL+n4*4];
        }
        __syncthreads();
        #pragma unroll
        for (int k=0;k<16;k++){
            float a[8];
            *(float4*)&a[0] = *(const float4*)&As[k*132 + ty*8];
            *(float4*)&a[4] = *(const float4*)&As[k*132 + ty*8 + 4];
            const ull* wp = (const ull*)&Ws[k*128 + tx*8];
            ull w2[4];
            #pragma unroll
            for (int j=0;j<4;j++) w2[j] = wp[j];
            #pragma unroll
            for (int i=0;i<8;i++){
                ull a2 = pack2(a[i]);
                #pragma unroll
                for (int j=0;j<4;j++) ffma2(c2[i][j], a2, w2[j]);
            }
        }
        __syncthreads();
    }

    int col0 = tx*8;
    float bv[8];
    *(float4*)&bv[0] = *(const float4*)&bias[col0];
    *(float4*)&bv[4] = *(const float4*)&bias[col0+4];
    #pragma unroll
    for (int i=0;i<8;i++){
        int row = m0 + ty*8 + i;
        float v[8];
        #pragma unroll
        for (int j=0;j<4;j++){ float2 f = *(float2*)&c2[i][j]; v[2*j]=f.x; v[2*j+1]=f.y; }
        #pragma unroll
        for (int jj=0;jj<8;jj++) v[jj] += bv[jj];
        if (relu_flag){
            #pragma unroll
            for (int jj=0;jj<8;jj++) v[jj] = fmaxf(v[jj], 0.f);
        }
        if (res_flag){
            float rv[8];
            *(float4*)&rv[0] = *(const float4*)&res[row*DMODEL+col0];
            *(float4*)&rv[4] = *(const float4*)&res[row*DMODEL+col0+4];
            #pragma unroll
            for (int jj=0;jj<8;jj++) v[jj] += rv[jj];
        }
        *(float4*)&C[row*DMODEL+col0]   = make_float4(v[0],v[1],v[2],v[3]);
        *(float4*)&C[row*DMODEL+col0+4] = make_float4(v[4],v[5],v[6],v[7]);
    }
}

// ---------------- layernorm over D=128, one row per block ------------------
__global__ void __launch_bounds__(128) ln_kernel(
    const float* __restrict__ x, const float* __restrict__ g,
    const float* __restrict__ b, float* __restrict__ y)
{
    int row = blockIdx.x;
    int d = threadIdx.x;
    float v = x[row*DMODEL + d];
    float s = v, sq = v*v;
    #pragma unroll
    for (int o=16;o;o>>=1){
        s  += __shfl_xor_sync(0xffffffffu, s,  o);
        sq += __shfl_xor_sync(0xffffffffu, sq, o);
    }
    __shared__ float sh[8];
    int w = d >> 5, lane = d & 31;
    if (lane == 0){ sh[w] = s; sh[4+w] = sq; }
    __syncthreads();
    float ts = sh[0]+sh[1]+sh[2]+sh[3];
    float tq = sh[4]+sh[5]+sh[6]+sh[7];
    float mean = ts * (1.f/DMODEL);
    float var  = tq * (1.f/DMODEL) - mean*mean;
    y[row*DMODEL + d] = (v - mean) * rsqrtf(var + 1e-5f) * g[d] + b[d];
}

// ---------------- depthwise conv k=7 ---------------------------------------
__global__ void __launch_bounds__(128) dw_kernel(
    const float* __restrict__ x, const float* __restrict__ w,
    const float* __restrict__ bias, float* __restrict__ y)
{
    int m = blockIdx.x;
    int d = threadIdx.x;
    int b = m / LSEQ;
    int l = m - b*LSEQ;
    float acc = bias[d];
    #pragma unroll
    for (int t=0;t<7;t++){
        int ll = l + t - 3;
        if (ll >= 0 && ll < LSEQ)
            acc += x[(b*LSEQ + ll)*DMODEL + d] * w[t*DMODEL + d];
    }
    y[m*DMODEL + d] = acc;
}

// ---------------- attention: one block per (b,h), 416 threads --------------
// K/V staged in SMEM in j-tiles of 100 (broadcast reads), FFMA2 dot/accum,
// online softmax across tiles with FMA-pipe exp.
#define JT 100
__global__ void __launch_bounds__(416) attn_kernel(
    const float* __restrict__ Q, const float* __restrict__ K,
    const float* __restrict__ V, float* __restrict__ O)
{
    __shared__ float2 Ks[JT][8];
    __shared__ float2 Vs[JT][8];
    int bh = blockIdx.x;
    int b = bh >> 3, h = bh & 7;
    int i = threadIdx.x;

    ull q2[8];
    if (i < LSEQ){
        const ull* qp = (const ull*)(Q + (b*LSEQ + i)*DMODEL + h*HDIM);
        #pragma unroll
        for (int p=0;p<8;p++) q2[p] = qp[p];
    }
    float m = -1e30f, ssum = 0.f;
    ull o2[8];
    #pragma unroll
    for (int p=0;p<8;p++) o2[p] = 0ull;

    for (int jt=0; jt<4; jt++){
        __syncthreads();
        for (int idx = threadIdx.x; idx < JT*8; idx += 416){
            int jj = idx >> 3, hd2 = idx & 7;
            int g = (b*LSEQ + jt*JT + jj)*(DMODEL/2) + h*8 + hd2;
            Ks[jj][hd2] = ((const float2*)K)[g];
            Vs[jj][hd2] = ((const float2*)V)[g];
        }
        __syncthreads();
        if (i < LSEQ){
            // pass 1: tile max
            float lm = -1e30f;
            for (int jj=0;jj<JT;jj++){
                ull acc = 0ull;
                const ull* kp = (const ull*)&Ks[jj][0];
                #pragma unroll
                for (int p=0;p<8;p++) ffma2(acc, q2[p], kp[p]);
                float2 af = *(float2*)&acc;
                float s = (af.x + af.y) * 0.25f;
                lm = fmaxf(lm, s);
            }
            float mn = fmaxf(m, lm);
            float corr = fexp(m - mn);
            ssum *= corr;
            ull corr2 = pack2(corr);
            #pragma unroll
            for (int p=0;p<8;p++) mul2(o2[p], corr2);
            // pass 2: accumulate
            for (int jj=0;jj<JT;jj++){
                ull acc = 0ull;
                const ull* kp = (const ull*)&Ks[jj][0];
                #pragma unroll
                for (int p=0;p<8;p++) ffma2(acc, q2[p], kp[p]);
                float2 af = *(float2*)&acc;
                float s = (af.x + af.y) * 0.25f;
                float pv = fexp(s - mn);
                ssum += pv;
                ull p2 = pack2(pv);
                const ull* vp = (const ull*)&Vs[jj][0];
                #pragma unroll
                for (int p=0;p<8;p++) ffma2(o2[p], p2, vp[p]);
            }
            m = mn;
        }
    }
    if (i < LSEQ){
        float inv = 1.f / ssum;
        float2* op = (float2*)(O + (b*LSEQ + i)*DMODEL + h*HDIM);
        #pragma unroll
        for (int p=0;p<8;p++){
            float2 f = *(float2*)&o2[p];
            op[p] = make_float2(f.x*inv, f.y*inv);
        }
    }
}

// ---------------- host orchestration ---------------------------------------
extern "C" void kernel_launch(void* const* d_in, const int* in_sizes, int n_in,
                              void* d_out, int out_size)
{
    const float* x        = (const float*)d_in[0];
    const float* w_init   = (const float*)d_in[1];
    const float* b_init   = (const float*)d_in[2];
    const float* ln_cg    = (const float*)d_in[3];
    const float* ln_cb    = (const float*)d_in[4];
    const float* w_dw     = (const float*)d_in[5];
    const float* b_dw     = (const float*)d_in[6];
    const float* w_pw     = (const float*)d_in[7];
    const float* b_pw     = (const float*)d_in[8];
    const float* ln_ag    = (const float*)d_in[9];
    const float* ln_ab    = (const float*)d_in[10];
    const float* wq       = (const float*)d_in[11];
    const float* bq       = (const float*)d_in[12];
    const float* wk       = (const float*)d_in[13];
    const float* bk       = (const float*)d_in[14];
    const float* wv       = (const float*)d_in[15];
    const float* bv       = (const float*)d_in[16];
    const float* wo       = (const float*)d_in[17];
    const float* bo       = (const float*)d_in[18];
    const float* ln_fg    = (const float*)d_in[19];
    const float* ln_fb    = (const float*)d_in[20];
    const float* w1       = (const float*)d_in[21];
    const float* b1       = (const float*)d_in[22];
    const float* w2       = (const float*)d_in[23];
    const float* b2       = (const float*)d_in[24];

    float *h, *ln, *tmp, *q, *k, *v, *att;
    cudaGetSymbolAddress((void**)&h,   g_h);
    cudaGetSymbolAddress((void**)&ln,  g_ln);
    cudaGetSymbolAddress((void**)&tmp, g_tmp);
    cudaGetSymbolAddress((void**)&q,   g_q);
    cudaGetSymbolAddress((void**)&k,   g_k);
    cudaGetSymbolAddress((void**)&v,   g_v);
    cudaGetSymbolAddress((void**)&att, g_att);

    // 1) pad x + posenc table
    pad_kernel<<<(BATCH*LPAD*CIN + 255)/256, 256>>>(x);
    pe_kernel<<<(LSEQ*DMODEL + 255)/256, 256>>>();

    // 2) init conv (implicit GEMM) + posenc -> h
    conv_gemm_kernel<<<MROWS/64, 128>>>(w_init, b_init, h);

    // 3) 4x depthwise-separable conv blocks
    for (int i=0;i<4;i++){
        ln_kernel<<<MROWS, 128>>>(h, ln_cg + i*DMODEL, ln_cb + i*DMODEL, ln);
        dw_kernel<<<MROWS, 128>>>(ln, w_dw + i*7*DMODEL, b_dw + i*DMODEL, tmp);
        gemm_kernel<<<MROWS/64, 128>>>(tmp, w_pw + i*DMODEL*DMODEL,
                                       b_pw + i*DMODEL, h, h, 1, 1);
    }

    // 4) attention
    ln_kernel<<<MROWS, 128>>>(h, ln_ag, ln_ab, ln);
    gemm_kernel<<<MROWS/64, 128>>>(ln, wq, bq, nullptr, q, 0, 0);
    gemm_kernel<<<MROWS/64, 128>>>(ln, wk, bk, nullptr, k, 0, 0);
    gemm_kernel<<<MROWS/64, 128>>>(ln, wv, bv, nullptr, v, 0, 0);
    attn_kernel<<<BATCH*NHEAD, 416>>>(q, k, v, att);
    gemm_kernel<<<MROWS/64, 128>>>(att, wo, bo, h, tmp, 0, 1);

    // 5) FFN -> d_out
    ln_kernel<<<MROWS, 128>>>(tmp, ln_fg, ln_fb, ln);
    gemm_kernel<<<MROWS/64, 128>>>(ln, w1, b1, nullptr, q, 1, 0);
    gemm_kernel<<<MROWS/64, 128>>>(q, w2, b2, tmp, (float*)d_out, 0, 1);
}

// round 6
// speedup vs baseline: 1.6152x; 1.6152x over previous
#include <cuda_runtime.h>
#include <cuda_bf16.h>
#include <cstdint>

typedef unsigned long long ull;

// Problem constants
#define BATCH 64
#define LSEQ  400
#define CIN   500
#define DMODEL 128
#define NHEAD 8
#define HDIM  16
#define MROWS (BATCH*LSEQ)          // 25600
#define LPAD  (LSEQ+4)              // 404
#define KCONV 2500                  // 5*500
#define CONV_CHUNKS 80              // K padded to 2560, BK=32
#define GEMM_CHUNKS 4               // K=128, BK=32
#define CONV_BWORDS (CONV_CHUNKS*2048)   // 163840
#define GEMM_BWORDS (GEMM_CHUNKS*2048)   // 8192 per matrix

// ---------------- scratch (static device globals; zero-initialized) --------
__device__ float g_xpad[BATCH*LPAD*CIN + 64];
__device__ float g_pe[LSEQ*DMODEL];
__device__ float g_h [MROWS*DMODEL];
__device__ float g_ln[MROWS*DMODEL];
__device__ float g_tmp[MROWS*DMODEL];
__device__ float g_q [MROWS*DMODEL];
__device__ float g_k [MROWS*DMODEL];
__device__ float g_v [MROWS*DMODEL];
__device__ float g_att[MROWS*DMODEL];

// pre-split weights, stored in HMMA B-fragment order, bf16x2 packed in u32
// [0, CONV_BWORDS): conv ; then 10 mats x GEMM_BWORDS
__device__ uint32_t g_bh[CONV_BWORDS + 10*GEMM_BWORDS];
__device__ uint32_t g_bl[CONV_BWORDS + 10*GEMM_BWORDS];

// ---------------- helpers ----------------------------------------------------
__device__ __forceinline__ ull pack2(float a){
    ull r; asm("mov.b64 %0, {%1, %1};" : "=l"(r) : "f"(a)); return r;
}
__device__ __forceinline__ void ffma2(ull& c, ull a, ull b){
    asm("fma.rn.f32x2 %0, %1, %2, %0;" : "+l"(c) : "l"(a), "l"(b));
}

// split two consecutive-k floats into packed bf16 hi / lo pairs (low 16b = first k)
__device__ __forceinline__ void split2(float f0, float f1, uint32_t& h, uint32_t& l){
    __nv_bfloat16 h0 = __float2bfloat16(f0);
    __nv_bfloat16 h1 = __float2bfloat16(f1);
    float r0 = f0 - __bfloat162float(h0);
    float r1 = f1 - __bfloat162float(h1);
    __nv_bfloat16 l0 = __float2bfloat16(r0);
    __nv_bfloat16 l1 = __float2bfloat16(r1);
    unsigned short hu0 = *(unsigned short*)&h0, hu1 = *(unsigned short*)&h1;
    unsigned short lu0 = *(unsigned short*)&l0, lu1 = *(unsigned short*)&l1;
    h = (uint32_t)hu0 | ((uint32_t)hu1 << 16);
    l = (uint32_t)lu0 | ((uint32_t)lu1 << 16);
}

__device__ __forceinline__ void mma_bf16(float* d, const uint32_t* a, const uint32_t* b){
    asm volatile(
        "mma.sync.aligned.m16n8k16.row.col.f32.bf16.bf16.f32 "
        "{%0,%1,%2,%3}, {%4,%5,%6,%7}, {%8,%9}, {%0,%1,%2,%3};"
        : "+f"(d[0]), "+f"(d[1]), "+f"(d[2]), "+f"(d[3])
        : "r"(a[0]), "r"(a[1]), "r"(a[2]), "r"(a[3]), "r"(b[0]), "r"(b[1]));
}

// ---------------- pad x into [B,404,500] (float4) ---------------------------
__global__ void __launch_bounds__(256) pad_kernel(const float* __restrict__ x){
    int idx = blockIdx.x*256 + threadIdx.x;
    if (idx >= BATCH*LPAD*(CIN/4)) return;
    int c4 = idx % (CIN/4);
    int rest = idx / (CIN/4);
    int lp = rest % LPAD;
    int b  = rest / LPAD;
    int l = lp - 2;
    float4 v = make_float4(0.f,0.f,0.f,0.f);
    if (l >= 0 && l < LSEQ) v = ((const float4*)x)[(b*LSEQ + l)*(CIN/4) + c4];
    ((float4*)g_xpad)[idx] = v;
}

// ---------------- positional encoding table ---------------------------------
__global__ void __launch_bounds__(256) pe_kernel(){
    int idx = blockIdx.x*256 + threadIdx.x;
    if (idx >= LSEQ*DMODEL) return;
    int l = idx / DMODEL;
    int d = idx % DMODEL;
    int j = d & ~1;
    float div = expf(-(float)j * (logf(10000.f)/(float)DMODEL));
    float ang = (float)l * div;
    g_pe[idx] = (d & 1) ? cosf(ang) : sinf(ang);
}

// ---------------- weight prep into HMMA B-fragment order ---------------------
// B tile per BK=32 chunk: word layout ((s*16 + nt)*32 + lane)*2 + j
//   n  = nt*8 + (lane>>2)
//   k2 = (lane&3) + j*4 + s*8  (+ ch*16) ; word packs bf16(k=2*k2), bf16(k=2*k2+1)
__global__ void __launch_bounds__(256) prep_w_kernel(
    const float* __restrict__ w_init, const float* __restrict__ w_pw,
    const float* __restrict__ wq, const float* __restrict__ wk,
    const float* __restrict__ wv, const float* __restrict__ wo,
    const float* __restrict__ w1, const float* __restrict__ w2)
{
    int flat = blockIdx.x*256 + threadIdx.x;
    const float* W; int K, ch, w2i, outoff;
    if (flat < CONV_BWORDS){
        W = w_init; K = KCONV;
        ch = flat >> 11; w2i = flat & 2047; outoff = flat;
    } else {
        int rem = flat - CONV_BWORDS;
        int m = rem >> 13;                 // matrix index 0..9
        int w2g = rem & 8191;
        ch = w2g >> 11; w2i = w2g & 2047;
        K = DMODEL; outoff = flat;
        switch (m){
            case 0: case 1: case 2: case 3: W = w_pw + m*DMODEL*DMODEL; break;
            case 4: W = wq; break; case 5: W = wk; break;
            case 6: W = wv; break; case 7: W = wo; break;
            case 8: W = w1; break; default: W = w2; break;
        }
    }
    int j    = w2i & 1;
    int lane = (w2i >> 1) & 31;
    int snt  = w2i >> 6;
    int nt   = snt & 15;
    int s    = snt >> 4;
    int n  = nt*8 + (lane >> 2);
    int k2 = (lane & 3) + j*4 + s*8 + ch*16;
    int k  = 2*k2;
    float v0 = (k   < K) ? W[(long)k    *DMODEL + n] : 0.f;
    float v1 = (k+1 < K) ? W[(long)(k+1)*DMODEL + n] : 0.f;
    uint32_t h, l;
    split2(v0, v1, h, l);
    g_bh[outoff] = h;
    g_bl[outoff] = l;
}

// ---------------- HMMA bf16x3 GEMM -------------------------------------------
// C[BM per CTA][128] = A[.,K] @ W[K,128]; 3-pass (hi*hi + lo*hi + hi*lo), fp32 acc.
// A smem: fragment order, word ((s*MT_CNT + mt)*32 + lane)*4 + j  (uint4/thread)
// CONV: A rows gathered from g_xpad (im2col flat); epilogue adds posenc.
template<int BM, int KCHUNKS, bool CONV, int MINB>
__global__ void __launch_bounds__(256, MINB) gemm_mma(
    const float* __restrict__ A,
    const uint32_t* __restrict__ Bhi, const uint32_t* __restrict__ Blo,
    const float* __restrict__ bias, const float* __restrict__ res,
    float* __restrict__ C, int relu_flag, int res_flag)
{
    constexpr int MT_CNT = BM/16;
    constexpr int WM_CNT = BM/32;       // warps along M
    constexpr int WN_CNT = 8/WM_CNT;    // warps along N
    constexpr int NTW    = 16/WN_CNT;   // n8-tiles per warp
    constexpr int NLOAD  = BM/32;       // float4 loads per thread per chunk

    __shared__ uint32_t sAhi[2*MT_CNT*32*4], sAlo[2*MT_CNT*32*4];
    __shared__ uint32_t sBhi[4096], sBlo[4096];   // 2 chunks' worth? no: 2048 used

    int t = threadIdx.x, lane = t & 31, wid = t >> 5;
    int m0 = blockIdx.x * BM;

    long abase[NLOAD]; int wordA[NLOAD]; int c4a[NLOAD];
    #pragma unroll
    for (int i = 0; i < NLOAD; i++){
        int idx = t*NLOAD + i;
        int row = idx >> 3, c4 = idx & 7;
        c4a[i] = c4;
        if (CONV){
            int m = m0 + row; int b = m / LSEQ; int l = m - b*LSEQ;
            abase[i] = (long)(b*LPAD + l) * CIN;
        } else {
            abase[i] = (long)(m0 + row) * DMODEL;
        }
        int mt = row >> 4, rl = row & 15, g = rl & 7, rbit = rl >> 3;
        int s  = c4 >> 2;
        int k2l = (c4*2) & 7;
        int t_ = k2l & 3, kbit = (k2l >> 2) & 1;
        int j = rbit + 2*kbit;
        wordA[i] = ((s*MT_CNT + mt)*32 + g*4 + t_)*4 + j;
    }

    float d[2][NTW][4];
    #pragma unroll
    for (int a=0;a<2;a++)
        #pragma unroll
        for (int b=0;b<NTW;b++)
            #pragma unroll
            for (int c=0;c<4;c++) d[a][b][c] = 0.f;

    int wm = wid % WM_CNT, wn = wid / WM_CNT;

    for (int ch = 0; ch < KCHUNKS; ch++){
        #pragma unroll
        for (int i = 0; i < NLOAD; i++){
            float4 f = *(const float4*)(A + abase[i] + ch*32 + c4a[i]*4);
            uint32_t h0,l0,h1,l1;
            split2(f.x, f.y, h0, l0);
            split2(f.z, f.w, h1, l1);
            sAhi[wordA[i]]   = h0;  sAhi[wordA[i]+4] = h1;
            sAlo[wordA[i]]   = l0;  sAlo[wordA[i]+4] = l1;
        }
        {
            const uint4* gh = (const uint4*)(Bhi + ch*2048);
            const uint4* gl = (const uint4*)(Blo + ch*2048);
            ((uint4*)sBhi)[t]     = gh[t];
            ((uint4*)sBhi)[t+256] = gh[t+256];
            ((uint4*)sBlo)[t]     = gl[t];
            ((uint4*)sBlo)[t+256] = gl[t+256];
        }
        __syncthreads();
        #pragma unroll
        for (int s = 0; s < 2; s++){
            uint4 ah[2], al[2];
            #pragma unroll
            for (int mt2 = 0; mt2 < 2; mt2++){
                int mt = wm*2 + mt2;
                ah[mt2] = ((const uint4*)sAhi)[(s*MT_CNT + mt)*32 + lane];
                al[mt2] = ((const uint4*)sAlo)[(s*MT_CNT + mt)*32 + lane];
            }
            #pragma unroll
            for (int nt = 0; nt < NTW; nt++){
                int ntg = wn*NTW + nt;
                uint2 bh = ((const uint2*)sBhi)[(s*16 + ntg)*32 + lane];
                uint2 bl = ((const uint2*)sBlo)[(s*16 + ntg)*32 + lane];
                #pragma unroll
                for (int mt2 = 0; mt2 < 2; mt2++){
                    mma_bf16(d[mt2][nt], (const uint32_t*)&ah[mt2], (const uint32_t*)&bh);
                    mma_bf16(d[mt2][nt], (const uint32_t*)&al[mt2], (const uint32_t*)&bh);
                    mma_bf16(d[mt2][nt], (const uint32_t*)&ah[mt2], (const uint32_t*)&bl);
                }
            }
        }
        __syncthreads();
    }

    // epilogue: d0,d1 -> (row g, cols 2t_,2t_+1); d2,d3 -> row g+8
    int g = lane >> 2, t_ = lane & 3;
    #pragma unroll
    for (int mt2 = 0; mt2 < 2; mt2++){
        int rbase = m0 + wm*32 + mt2*16 + g;
        #pragma unroll
        for (int hf = 0; hf < 2; hf++){
            int row = rbase + hf*8;
            const float* pe = CONV ? (g_pe + (long)(row % LSEQ)*DMODEL) : (const float*)0;
            #pragma unroll
            for (int nt = 0; nt < NTW; nt++){
                int col = wn*(NTW*8) + nt*8 + t_*2;
                float v0 = d[mt2][nt][hf*2+0];
                float v1 = d[mt2][nt][hf*2+1];
                float2 bb = *(const float2*)(bias + col);
                v0 += bb.x; v1 += bb.y;
                if (CONV){
                    float2 p = *(const float2*)(pe + col);
                    v0 += p.x; v1 += p.y;
                }
                if (relu_flag){ v0 = fmaxf(v0, 0.f); v1 = fmaxf(v1, 0.f); }
                if (res_flag){
                    float2 r = *(const float2*)(res + (long)row*DMODEL + col);
                    v0 += r.x; v1 += r.y;
                }
                *(float2*)(C + (long)row*DMODEL + col) = make_float2(v0, v1);
            }
        }
    }
}

// ---------------- layernorm: one warp per row, float4 ------------------------
__global__ void __launch_bounds__(256) ln_kernel(
    const float* __restrict__ x, const float* __restrict__ g,
    const float* __restrict__ b, float* __restrict__ y)
{
    int t = threadIdx.x;
    int row = blockIdx.x*8 + (t >> 5);
    int lane = t & 31;
    float4 v = ((const float4*)x)[row*32 + lane];
    float s  = v.x + v.y + v.z + v.w;
    float sq = v.x*v.x + v.y*v.y + v.z*v.z + v.w*v.w;
    #pragma unroll
    for (int o = 16; o; o >>= 1){
        s  += __shfl_xor_sync(0xffffffffu, s,  o);
        sq += __shfl_xor_sync(0xffffffffu, sq, o);
    }
    float mean = s * (1.f/DMODEL);
    float var  = sq * (1.f/DMODEL) - mean*mean;
    float rs = rsqrtf(var + 1e-5f);
    float4 gg = ((const float4*)g)[lane];
    float4 bb = ((const float4*)b)[lane];
    float4 o4;
    o4.x = (v.x-mean)*rs*gg.x + bb.x;
    o4.y = (v.y-mean)*rs*gg.y + bb.y;
    o4.z = (v.z-mean)*rs*gg.z + bb.z;
    o4.w = (v.w-mean)*rs*gg.w + bb.w;
    ((float4*)y)[row*32 + lane] = o4;
}

// ---------------- depthwise conv k=7 (float4 over D) -------------------------
__global__ void __launch_bounds__(128) dw_kernel(
    const float* __restrict__ x, const float* __restrict__ w,
    const float* __restrict__ bias, float* __restrict__ y)
{
    int t = threadIdx.x;
    int m = blockIdx.x*4 + (t >> 5);
    int d4 = t & 31;
    int b = m / LSEQ;
    int l = m - b*LSEQ;
    float4 acc = ((const float4*)bias)[d4];
    #pragma unroll
    for (int tap = 0; tap < 7; tap++){
        int ll = l + tap - 3;
        if (ll >= 0 && ll < LSEQ){
            float4 xv = ((const float4*)x)[(b*LSEQ + ll)*32 + d4];
            float4 wv = ((const float4*)w)[tap*32 + d4];
            acc.x += xv.x*wv.x; acc.y += xv.y*wv.y;
            acc.z += xv.z*wv.z; acc.w += xv.w*wv.w;
        }
    }
    ((float4*)y)[m*32 + d4] = acc;
}

// ---------------- attention: single-pass (scores bounded, exp identity) ------
#define JT 100
__global__ void __launch_bounds__(416) attn_kernel(
    const float* __restrict__ Q, const float* __restrict__ K,
    const float* __restrict__ V, float* __restrict__ O)
{
    __shared__ float2 Ks[JT][8];
    __shared__ float2 Vs[JT][8];
    int bh = blockIdx.x;
    int b = bh >> 3, h = bh & 7;
    int i = threadIdx.x;

    ull q2[8];
    if (i < LSEQ){
        const ull* qp = (const ull*)(Q + (b*LSEQ + i)*DMODEL + h*HDIM);
        #pragma unroll
        for (int p = 0; p < 8; p++) q2[p] = qp[p];
    }
    float ssum = 0.f;
    ull o2[8];
    #pragma unroll
    for (int p = 0; p < 8; p++) o2[p] = 0ull;

    for (int jt = 0; jt < 4; jt++){
        __syncthreads();
        for (int idx = threadIdx.x; idx < JT*8; idx += 416){
            int jj = idx >> 3, hd2 = idx & 7;
            int gidx = (b*LSEQ + jt*JT + jj)*(DMODEL/2) + h*8 + hd2;
            Ks[jj][hd2] = ((const float2*)K)[gidx];
            Vs[jj][hd2] = ((const float2*)V)[gidx];
        }
        __syncthreads();
        if (i < LSEQ){
            for (int jj = 0; jj < JT; jj++){
                ull acc = 0ull;
                const ull* kp = (const ull*)&Ks[jj][0];
                #pragma unroll
                for (int p = 0; p < 8; p++) ffma2(acc, q2[p], kp[p]);
                float2 af = *(float2*)&acc;
                float s = (af.x + af.y) * 0.25f;
                float pv = __expf(s);          // MUFU EX2 — off the FMA pipe
                ssum += pv;
                ull p2 = pack2(pv);
                const ull* vp = (const ull*)&Vs[jj][0];
                #pragma unroll
                for (int p = 0; p < 8; p++) ffma2(o2[p], p2, vp[p]);
            }
        }
    }
    if (i < LSEQ){
        float inv = 1.f / ssum;
        float2* op = (float2*)(O + (b*LSEQ + i)*DMODEL + h*HDIM);
        #pragma unroll
        for (int p = 0; p < 8; p++){
            float2 f = *(float2*)&o2[p];
            op[p] = make_float2(f.x*inv, f.y*inv);
        }
    }
}

// ---------------- host orchestration ----------------------------------------
extern "C" void kernel_launch(void* const* d_in, const int* in_sizes, int n_in,
                              void* d_out, int out_size)
{
    const float* x      = (const float*)d_in[0];
    const float* w_init = (const float*)d_in[1];
    const float* b_init = (const float*)d_in[2];
    const float* ln_cg  = (const float*)d_in[3];
    const float* ln_cb  = (const float*)d_in[4];
    const float* w_dw   = (const float*)d_in[5];
    const float* b_dw   = (const float*)d_in[6];
    const float* w_pw   = (const float*)d_in[7];
    const float* b_pw   = (const float*)d_in[8];
    const float* ln_ag  = (const float*)d_in[9];
    const float* ln_ab  = (const float*)d_in[10];
    const float* wq     = (const float*)d_in[11];
    const float* bq     = (const float*)d_in[12];
    const float* wk     = (const float*)d_in[13];
    const float* bk     = (const float*)d_in[14];
    const float* wv     = (const float*)d_in[15];
    const float* bv     = (const float*)d_in[16];
    const float* wo     = (const float*)d_in[17];
    const float* bo     = (const float*)d_in[18];
    const float* ln_fg  = (const float*)d_in[19];
    const float* ln_fb  = (const float*)d_in[20];
    const float* w1     = (const float*)d_in[21];
    const float* b1     = (const float*)d_in[22];
    const float* w2     = (const float*)d_in[23];
    const float* b2     = (const float*)d_in[24];

    float *xpad, *h, *ln, *tmp, *q, *k, *v, *att;
    uint32_t *bh, *bl;
    cudaGetSymbolAddress((void**)&xpad, g_xpad);
    cudaGetSymbolAddress((void**)&h,    g_h);
    cudaGetSymbolAddress((void**)&ln,   g_ln);
    cudaGetSymbolAddress((void**)&tmp,  g_tmp);
    cudaGetSymbolAddress((void**)&q,    g_q);
    cudaGetSymbolAddress((void**)&k,    g_k);
    cudaGetSymbolAddress((void**)&v,    g_v);
    cudaGetSymbolAddress((void**)&att,  g_att);
    cudaGetSymbolAddress((void**)&bh,   g_bh);
    cudaGetSymbolAddress((void**)&bl,   g_bl);

    // 1) pad x, posenc, weight prep
    pad_kernel<<<(BATCH*LPAD*(CIN/4) + 255)/256, 256>>>(x);
    pe_kernel<<<(LSEQ*DMODEL + 255)/256, 256>>>();
    prep_w_kernel<<<(CONV_BWORDS + 10*GEMM_BWORDS)/256, 256>>>(
        w_init, w_pw, wq, wk, wv, wo, w1, w2);

    // 2) init conv (implicit GEMM on HMMA) + posenc -> h  (BM=64, grid 400)
    gemm_mma<64, CONV_CHUNKS, true, 3><<<MROWS/64, 256>>>(
        xpad, bh, bl, b_init, nullptr, h, 0, 0);

    #define GW(m) (bh + CONV_BWORDS + (m)*GEMM_BWORDS), (bl + CONV_BWORDS + (m)*GEMM_BWORDS)

    // 3) 4x depthwise-separable conv blocks
    for (int i = 0; i < 4; i++){
        ln_kernel<<<MROWS/8, 256>>>(h, ln_cg + i*DMODEL, ln_cb + i*DMODEL, ln);
        dw_kernel<<<MROWS/4, 128>>>(ln, w_dw + i*7*DMODEL, b_dw + i*DMODEL, tmp);
        gemm_mma<128, GEMM_CHUNKS, false, 2><<<MROWS/128, 256>>>(
            tmp, GW(i), b_pw + i*DMODEL, h, h, 1, 1);
    }

    // 4) attention
    ln_kernel<<<MROWS/8, 256>>>(h, ln_ag, ln_ab, ln);
    gemm_mma<128, GEMM_CHUNKS, false, 2><<<MROWS/128, 256>>>(
        ln, GW(4), bq, nullptr, q, 0, 0);
    gemm_mma<128, GEMM_CHUNKS, false, 2><<<MROWS/128, 256>>>(
        ln, GW(5), bk, nullptr, k, 0, 0);
    gemm_mma<128, GEMM_CHUNKS, false, 2><<<MROWS/128, 256>>>(
        ln, GW(6), bv, nullptr, v, 0, 0);
    attn_kernel<<<BATCH*NHEAD, 416>>>(q, k, v, att);
    gemm_mma<128, GEMM_CHUNKS, false, 2><<<MROWS/128, 256>>>(
        att, GW(7), bo, h, tmp, 0, 1);

    // 5) FFN -> d_out
    ln_kernel<<<MROWS/8, 256>>>(tmp, ln_fg, ln_fb, ln);
    gemm_mma<128, GEMM_CHUNKS, false, 2><<<MROWS/128, 256>>>(
        ln, GW(8), b1, nullptr, q, 1, 0);
    gemm_mma<128, GEMM_CHUNKS, false, 2><<<MROWS/128, 256>>>(
        q, GW(9), b2, tmp, (float*)d_out, 0, 1);
}

// round 7
// speedup vs baseline: 1.7922x; 1.1096x over previous
#include <cuda_runtime.h>
#include <cuda_fp16.h>
#include <cstdint>

typedef unsigned long long ull;

// Problem constants
#define BATCH 64
#define LSEQ  400
#define CIN   500
#define DMODEL 128
#define NHEAD 8
#define HDIM  16
#define MROWS (BATCH*LSEQ)          // 25600
#define LPAD  (LSEQ+4)              // 404
#define KCONV 2500                  // 5*500
#define CONV_CHUNKS 80              // K padded to 2560, BK=32
#define GEMM_CHUNKS 4               // K=128, BK=32
#define CONV_BWORDS (CONV_CHUNKS*2048)   // 163840
#define GEMM_BWORDS (GEMM_CHUNKS*2048)   // 8192 per matrix

// ---------------- scratch (static device globals; zero-initialized) --------
__device__ float g_xpad[BATCH*LPAD*CIN + 64];
__device__ float g_pe[LSEQ*DMODEL];
__device__ float g_h [MROWS*DMODEL];
__device__ float g_ln[MROWS*DMODEL];
__device__ float g_tmp[MROWS*DMODEL];
__device__ float g_q [MROWS*DMODEL];
__device__ float g_k [MROWS*DMODEL];
__device__ float g_v [MROWS*DMODEL];
__device__ float g_att[MROWS*DMODEL];

// pre-split weights in HMMA B-fragment order, fp16x2 packed in u32
__device__ uint32_t g_bh[CONV_BWORDS + 10*GEMM_BWORDS];
__device__ uint32_t g_bl[CONV_BWORDS + 10*GEMM_BWORDS];

// ---------------- helpers ----------------------------------------------------
__device__ __forceinline__ uint32_t smem_u32(const void* p){
    uint32_t a;
    asm("{ .reg .u64 t; cvta.to.shared.u64 t, %1; cvt.u32.u64 %0, t; }"
        : "=r"(a) : "l"(p));
    return a;
}
__device__ __forceinline__ ull pack2(float a){
    ull r; asm("mov.b64 %0, {%1, %1};" : "=l"(r) : "f"(a)); return r;
}
__device__ __forceinline__ void ffma2(ull& c, ull a, ull b){
    asm("fma.rn.f32x2 %0, %1, %2, %0;" : "+l"(c) : "l"(a), "l"(b));
}

// split two consecutive-k floats into packed fp16 hi / lo pairs (low 16b = first k)
__device__ __forceinline__ void split2(float f0, float f1, uint32_t& h, uint32_t& l){
    __half h0 = __float2half_rn(f0);
    __half h1 = __float2half_rn(f1);
    float r0 = f0 - __half2float(h0);
    float r1 = f1 - __half2float(h1);
    __half l0 = __float2half_rn(r0);
    __half l1 = __float2half_rn(r1);
    unsigned short hu0 = *(unsigned short*)&h0, hu1 = *(unsigned short*)&h1;
    unsigned short lu0 = *(unsigned short*)&l0, lu1 = *(unsigned short*)&l1;
    h = (uint32_t)hu0 | ((uint32_t)hu1 << 16);
    l = (uint32_t)lu0 | ((uint32_t)lu1 << 16);
}

__device__ __forceinline__ void mma_f16(float* d, const uint32_t* a, const uint32_t* b){
    asm volatile(
        "mma.sync.aligned.m16n8k16.row.col.f32.f16.f16.f32 "
        "{%0,%1,%2,%3}, {%4,%5,%6,%7}, {%8,%9}, {%0,%1,%2,%3};"
        : "+f"(d[0]), "+f"(d[1]), "+f"(d[2]), "+f"(d[3])
        : "r"(a[0]), "r"(a[1]), "r"(a[2]), "r"(a[3]), "r"(b[0]), "r"(b[1]));
}

__device__ __forceinline__ void cp16(uint32_t daddr, const void* gptr){
    asm volatile("cp.async.cg.shared.global [%0], [%1], 16;"
                 :: "r"(daddr), "l"(gptr) : "memory");
}
__device__ __forceinline__ void cp_commit(){
    asm volatile("cp.async.commit_group;" ::: "memory");
}
__device__ __forceinline__ void cp_wait0(){
    asm volatile("cp.async.wait_group 0;" ::: "memory");
}

// ---------------- pad x into [B,404,500] (float4) ---------------------------
__global__ void __launch_bounds__(256) pad_kernel(const float* __restrict__ x){
    int idx = blockIdx.x*256 + threadIdx.x;
    if (idx >= BATCH*LPAD*(CIN/4)) return;
    int c4 = idx % (CIN/4);
    int rest = idx / (CIN/4);
    int lp = rest % LPAD;
    int b  = rest / LPAD;
    int l = lp - 2;
    float4 v = make_float4(0.f,0.f,0.f,0.f);
    if (l >= 0 && l < LSEQ) v = ((const float4*)x)[(b*LSEQ + l)*(CIN/4) + c4];
    ((float4*)g_xpad)[idx] = v;
}

// ---------------- positional encoding table ---------------------------------
__global__ void __launch_bounds__(256) pe_kernel(){
    int idx = blockIdx.x*256 + threadIdx.x;
    if (idx >= LSEQ*DMODEL) return;
    int l = idx / DMODEL;
    int d = idx % DMODEL;
    int j = d & ~1;
    float div = expf(-(float)j * (logf(10000.f)/(float)DMODEL));
    float ang = (float)l * div;
    g_pe[idx] = (d & 1) ? cosf(ang) : sinf(ang);
}

// ---------------- weight prep into HMMA B-fragment order (fp16 hi/lo) --------
__global__ void __launch_bounds__(256) prep_w_kernel(
    const float* __restrict__ w_init, const float* __restrict__ w_pw,
    const float* __restrict__ wq, const float* __restrict__ wk,
    const float* __restrict__ wv, const float* __restrict__ wo,
    const float* __restrict__ w1, const float* __restrict__ w2)
{
    int flat = blockIdx.x*256 + threadIdx.x;
    const float* W; int K, ch, w2i;
    if (flat < CONV_BWORDS){
        W = w_init; K = KCONV;
        ch = flat >> 11; w2i = flat & 2047;
    } else {
        int rem = flat - CONV_BWORDS;
        int m = rem >> 13;
        int w2g = rem & 8191;
        ch = w2g >> 11; w2i = w2g & 2047;
        K = DMODEL;
        switch (m){
            case 0: case 1: case 2: case 3: W = w_pw + m*DMODEL*DMODEL; break;
            case 4: W = wq; break; case 5: W = wk; break;
            case 6: W = wv; break; case 7: W = wo; break;
            case 8: W = w1; break; default: W = w2; break;
        }
    }
    int j    = w2i & 1;
    int lane = (w2i >> 1) & 31;
    int snt  = w2i >> 6;
    int nt   = snt & 15;
    int s    = snt >> 4;
    int n  = nt*8 + (lane >> 2);
    int k2 = (lane & 3) + j*4 + s*8 + ch*16;
    int k  = 2*k2;
    float v0 = (k   < K) ? W[(long)k    *DMODEL + n] : 0.f;
    float v1 = (k+1 < K) ? W[(long)(k+1)*DMODEL + n] : 0.f;
    uint32_t h, l;
    split2(v0, v1, h, l);
    g_bh[flat] = h;
    g_bl[flat] = l;
}

// ---------------- pipelined HMMA fp16-split GEMM -----------------------------
// C[BM per CTA][128] = A[.,K] @ W[K,128]
// PASSES=2: Ahi*Bhi + Alo*Bhi (conv, err ~2^-12); PASSES=3: + Ahi*Blo (err ~2^-22)
// 2-stage smem pipeline: cp.async.cg for B (L1 bypass), reg-prefetched A.
template<int BM, int KCHUNKS, bool CONV, int PASSES>
__global__ void __launch_bounds__(256, 2) gemm_mma(
    const float* __restrict__ A,
    const uint32_t* __restrict__ Bhi, const uint32_t* __restrict__ Blo,
    const float* __restrict__ bias, const float* __restrict__ res,
    float* __restrict__ C, int relu_flag, int res_flag)
{
    constexpr int MT_CNT = BM/16;
    constexpr int WM_CNT = BM/32;
    constexpr int WN_CNT = 8/WM_CNT;
    constexpr int NTW    = 16/WN_CNT;
    constexpr int NLOAD  = BM/32;
    constexpr int AW = 256*MT_CNT;     // words per A stage per array
    constexpr int BW = 2048;           // words per B stage per array

    extern __shared__ uint32_t sm[];
    uint32_t* sAhi = sm;               // 2*AW
    uint32_t* sAlo = sm + 2*AW;        // 2*AW
    uint32_t* sBhi = sm + 4*AW;        // 2*BW
    uint32_t* sBlo = sm + 4*AW + 2*BW; // 2*BW (PASSES==3 only)
    uint32_t sb_bhi = smem_u32(sBhi);
    uint32_t sb_blo = smem_u32(sBlo);

    int t = threadIdx.x, lane = t & 31, wid = t >> 5;
    int m0 = blockIdx.x * BM;

    long abase[NLOAD]; int wordA[NLOAD]; int c4a[NLOAD];
    #pragma unroll
    for (int i = 0; i < NLOAD; i++){
        int idx = t*NLOAD + i;
        int row = idx >> 3, c4 = idx & 7;
        c4a[i] = c4;
        if (CONV){
            int m = m0 + row; int b = m / LSEQ; int l = m - b*LSEQ;
            abase[i] = (long)(b*LPAD + l) * CIN;
        } else {
            abase[i] = (long)(m0 + row) * DMODEL;
        }
        int mt = row >> 4, rl = row & 15, g = rl & 7, rbit = rl >> 3;
        int s  = c4 >> 2;
        int k2l = (c4*2) & 7;
        int t_ = k2l & 3, kbit = (k2l >> 2) & 1;
        int j = rbit + 2*kbit;
        wordA[i] = ((s*MT_CNT + mt)*32 + g*4 + t_)*4 + j;
    }

    float4 rA[NLOAD];
    float d[2][NTW][4];
    #pragma unroll
    for (int a=0;a<2;a++)
        #pragma unroll
        for (int b=0;b<NTW;b++)
            #pragma unroll
            for (int c=0;c<4;c++) d[a][b][c] = 0.f;

    int wm = wid % WM_CNT, wn = wid / WM_CNT;

    // prolog
    #pragma unroll
    for (int i=0;i<NLOAD;i++)
        rA[i] = *(const float4*)(A + abase[i] + 0*32 + c4a[i]*4);
    {
        const uint4* gh = (const uint4*)(Bhi);
        cp16(sb_bhi + (uint32_t)t*16,        gh + t);
        cp16(sb_bhi + (uint32_t)(t+256)*16,  gh + t + 256);
        if (PASSES == 3){
            const uint4* gl = (const uint4*)(Blo);
            cp16(sb_blo + (uint32_t)t*16,       gl + t);
            cp16(sb_blo + (uint32_t)(t+256)*16, gl + t + 256);
        }
        cp_commit();
    }
    #pragma unroll
    for (int i=0;i<NLOAD;i++){
        uint32_t h0,l0,h1,l1;
        split2(rA[i].x, rA[i].y, h0, l0);
        split2(rA[i].z, rA[i].w, h1, l1);
        sAhi[wordA[i]] = h0; sAhi[wordA[i]+4] = h1;
        sAlo[wordA[i]] = l0; sAlo[wordA[i]+4] = l1;
    }
    if (KCHUNKS > 1){
        #pragma unroll
        for (int i=0;i<NLOAD;i++)
            rA[i] = *(const float4*)(A + abase[i] + 1*32 + c4a[i]*4);
    }
    cp_wait0(); __syncthreads();

    #pragma unroll 2
    for (int ch = 0; ch < KCHUNKS; ch++){
        int cur = ch & 1, nxt = cur ^ 1;
        if (ch + 1 < KCHUNKS){
            // stage A(ch+1) into nxt
            #pragma unroll
            for (int i=0;i<NLOAD;i++){
                uint32_t h0,l0,h1,l1;
                split2(rA[i].x, rA[i].y, h0, l0);
                split2(rA[i].z, rA[i].w, h1, l1);
                uint32_t* dh = sAhi + nxt*AW;
                uint32_t* dl = sAlo + nxt*AW;
                dh[wordA[i]] = h0; dh[wordA[i]+4] = h1;
                dl[wordA[i]] = l0; dl[wordA[i]+4] = l1;
            }
            // stage B(ch+1) into nxt
            const uint4* gh = (const uint4*)(Bhi + (long)(ch+1)*BW);
            uint32_t dsth = sb_bhi + (uint32_t)nxt*BW*4;
            cp16(dsth + (uint32_t)t*16,       gh + t);
            cp16(dsth + (uint32_t)(t+256)*16, gh + t + 256);
            if (PASSES == 3){
                const uint4* gl = (const uint4*)(Blo + (long)(ch+1)*BW);
                uint32_t dstl = sb_blo + (uint32_t)nxt*BW*4;
                cp16(dstl + (uint32_t)t*16,       gl + t);
                cp16(dstl + (uint32_t)(t+256)*16, gl + t + 256);
            }
            cp_commit();
            if (ch + 2 < KCHUNKS){
                #pragma unroll
                for (int i=0;i<NLOAD;i++)
                    rA[i] = *(const float4*)(A + abase[i] + (long)(ch+2)*32 + c4a[i]*4);
            }
        }
        // compute on cur
        {
            const uint4* pAh = (const uint4*)(sAhi + cur*AW);
            const uint4* pAl = (const uint4*)(sAlo + cur*AW);
            const uint2* pBh = (const uint2*)(sBhi + cur*BW);
            const uint2* pBl = (const uint2*)(sBlo + cur*BW);
            #pragma unroll
            for (int s = 0; s < 2; s++){
                uint4 ah[2], al[2];
                #pragma unroll
                for (int mt2 = 0; mt2 < 2; mt2++){
                    int mt = wm*2 + mt2;
                    ah[mt2] = pAh[(s*MT_CNT + mt)*32 + lane];
                    al[mt2] = pAl[(s*MT_CNT + mt)*32 + lane];
                }
                #pragma unroll
                for (int nt = 0; nt < NTW; nt++){
                    int ntg = wn*NTW + nt;
                    uint2 bh = pBh[(s*16 + ntg)*32 + lane];
                    #pragma unroll
                    for (int mt2 = 0; mt2 < 2; mt2++){
                        mma_f16(d[mt2][nt], (const uint32_t*)&ah[mt2], (const uint32_t*)&bh);
                        mma_f16(d[mt2][nt], (const uint32_t*)&al[mt2], (const uint32_t*)&bh);
                    }
                    if (PASSES == 3){
                        uint2 bl = pBl[(s*16 + ntg)*32 + lane];
                        #pragma unroll
                        for (int mt2 = 0; mt2 < 2; mt2++)
                            mma_f16(d[mt2][nt], (const uint32_t*)&ah[mt2], (const uint32_t*)&bl);
                    }
                }
            }
        }
        if (ch + 1 < KCHUNKS){ cp_wait0(); __syncthreads(); }
    }

    // epilogue
    int g = lane >> 2, t_ = lane & 3;
    #pragma unroll
    for (int mt2 = 0; mt2 < 2; mt2++){
        int rbase = m0 + wm*32 + mt2*16 + g;
        #pragma unroll
        for (int hf = 0; hf < 2; hf++){
            int row = rbase + hf*8;
            const float* pe = CONV ? (g_pe + (long)(row % LSEQ)*DMODEL) : (const float*)0;
            #pragma unroll
            for (int nt = 0; nt < NTW; nt++){
                int col = wn*(NTW*8) + nt*8 + t_*2;
                float v0 = d[mt2][nt][hf*2+0];
                float v1 = d[mt2][nt][hf*2+1];
                float2 bb = *(const float2*)(bias + col);
                v0 += bb.x; v1 += bb.y;
                if (CONV){
                    float2 p = *(const float2*)(pe + col);
                    v0 += p.x; v1 += p.y;
                }
                if (relu_flag){ v0 = fmaxf(v0, 0.f); v1 = fmaxf(v1, 0.f); }
                if (res_flag){
                    float2 r = *(const float2*)(res + (long)row*DMODEL + col);
                    v0 += r.x; v1 += r.y;
                }
                *(float2*)(C + (long)row*DMODEL + col) = make_float2(v0, v1);
            }
        }
    }
}

// ---------------- layernorm: one warp per row, float4 ------------------------
__global__ void __launch_bounds__(256) ln_kernel(
    const float* __restrict__ x, const float* __restrict__ g,
    const float* __restrict__ b, float* __restrict__ y)
{
    int t = threadIdx.x;
    int row = blockIdx.x*8 + (t >> 5);
    int lane = t & 31;
    float4 v = ((const float4*)x)[row*32 + lane];
    float s  = v.x + v.y + v.z + v.w;
    float sq = v.x*v.x + v.y*v.y + v.z*v.z + v.w*v.w;
    #pragma unroll
    for (int o = 16; o; o >>= 1){
        s  += __shfl_xor_sync(0xffffffffu, s,  o);
        sq += __shfl_xor_sync(0xffffffffu, sq, o);
    }
    float mean = s * (1.f/DMODEL);
    float var  = sq * (1.f/DMODEL) - mean*mean;
    float rs = rsqrtf(var + 1e-5f);
    float4 gg = ((const float4*)g)[lane];
    float4 bb = ((const float4*)b)[lane];
    float4 o4;
    o4.x = (v.x-mean)*rs*gg.x + bb.x;
    o4.y = (v.y-mean)*rs*gg.y + bb.y;
    o4.z = (v.z-mean)*rs*gg.z + bb.z;
    o4.w = (v.w-mean)*rs*gg.w + bb.w;
    ((float4*)y)[row*32 + lane] = o4;
}

// ---------------- fused layernorm + depthwise conv k=7 -----------------------
// block: (batch, 50-row l-slab). LN 56 rows (incl 3-row halo, zero-padded)
// into smem, then dw-conv 50 rows from smem. Saves a full global round trip.
__global__ void __launch_bounds__(256) lndw_kernel(
    const float* __restrict__ x, const float* __restrict__ g,
    const float* __restrict__ b, const float* __restrict__ wdw,
    const float* __restrict__ bdw, float* __restrict__ y)
{
    __shared__ float4 sln[56][32];
    int blk = blockIdx.x;
    int bidx = blk >> 3, lb = blk & 7;
    int l0 = lb * 50;
    int t = threadIdx.x, wid = t >> 5, lane = t & 31;

    float4 gg = ((const float4*)g)[lane];
    float4 bb = ((const float4*)b)[lane];

    #pragma unroll
    for (int rr = 0; rr < 7; rr++){
        int r = wid + rr*8;
        int l = l0 - 3 + r;
        float4 o4 = make_float4(0.f,0.f,0.f,0.f);
        if (l >= 0 && l < LSEQ){
            float4 v = ((const float4*)x)[(bidx*LSEQ + l)*32 + lane];
            float s  = v.x + v.y + v.z + v.w;
            float sq = v.x*v.x + v.y*v.y + v.z*v.z + v.w*v.w;
            #pragma unroll
            for (int o = 16; o; o >>= 1){
                s  += __shfl_xor_sync(0xffffffffu, s,  o);
                sq += __shfl_xor_sync(0xffffffffu, sq, o);
            }
            float mean = s * (1.f/DMODEL);
            float var  = sq * (1.f/DMODEL) - mean*mean;
            float rs = rsqrtf(var + 1e-5f);
            o4.x = (v.x-mean)*rs*gg.x + bb.x;
            o4.y = (v.y-mean)*rs*gg.y + bb.y;
            o4.z = (v.z-mean)*rs*gg.z + bb.z;
            o4.w = (v.w-mean)*rs*gg.w + bb.w;
        }
        sln[r][lane] = o4;
    }
    __syncthreads();

    float4 wv[7];
    #pragma unroll
    for (int tap = 0; tap < 7; tap++) wv[tap] = ((const float4*)wdw)[tap*32 + lane];
    float4 bias4 = ((const float4*)bdw)[lane];

    #pragma unroll
    for (int rr = 0; rr < 7; rr++){
        int r = wid + rr*8;
        if (r < 50){
            float4 acc = bias4;
            #pragma unroll
            for (int tap = 0; tap < 7; tap++){
                float4 xv = sln[r + tap][lane];
                acc.x += xv.x*wv[tap].x; acc.y += xv.y*wv[tap].y;
                acc.z += xv.z*wv[tap].z; acc.w += xv.w*wv[tap].w;
            }
            ((float4*)y)[(bidx*LSEQ + l0 + r)*32 + lane] = acc;
        }
    }
}

// ---------------- attention: single-pass (scores bounded, exp identity) ------
#define JT 100
__global__ void __launch_bounds__(416) attn_kernel(
    const float* __restrict__ Q, const float* __restrict__ K,
    const float* __restrict__ V, float* __restrict__ O)
{
    __shared__ float2 Ks[JT][8];
    __shared__ float2 Vs[JT][8];
    int bh = blockIdx.x;
    int b = bh >> 3, h = bh & 7;
    int i = threadIdx.x;

    ull q2[8];
    if (i < LSEQ){
        const ull* qp = (const ull*)(Q + (b*LSEQ + i)*DMODEL + h*HDIM);
        #pragma unroll
        for (int p = 0; p < 8; p++) q2[p] = qp[p];
    }
    float ssum = 0.f;
    ull o2[8];
    #pragma unroll
    for (int p = 0; p < 8; p++) o2[p] = 0ull;

    for (int jt = 0; jt < 4; jt++){
        __syncthreads();
        for (int idx = threadIdx.x; idx < JT*8; idx += 416){
            int jj = idx >> 3, hd2 = idx & 7;
            int gidx = (b*LSEQ + jt*JT + jj)*(DMODEL/2) + h*8 + hd2;
            Ks[jj][hd2] = ((const float2*)K)[gidx];
            Vs[jj][hd2] = ((const float2*)V)[gidx];
        }
        __syncthreads();
        if (i < LSEQ){
            for (int jj = 0; jj < JT; jj++){
                ull acc = 0ull;
                const ull* kp = (const ull*)&Ks[jj][0];
                #pragma unroll
                for (int p = 0; p < 8; p++) ffma2(acc, q2[p], kp[p]);
                float2 af = *(float2*)&acc;
                float s = (af.x + af.y) * 0.25f;
                float pv = __expf(s);          // MUFU EX2 — off the FMA pipe
                ssum += pv;
                ull p2 = pack2(pv);
                const ull* vp = (const ull*)&Vs[jj][0];
                #pragma unroll
                for (int p = 0; p < 8; p++) ffma2(o2[p], p2, vp[p]);
            }
        }
    }
    if (i < LSEQ){
        float inv = 1.f / ssum;
        float2* op = (float2*)(O + (b*LSEQ + i)*DMODEL + h*HDIM);
        #pragma unroll
        for (int p = 0; p < 8; p++){
            float2 f = *(float2*)&o2[p];
            op[p] = make_float2(f.x*inv, f.y*inv);
        }
    }
}

// ---------------- host orchestration ----------------------------------------
#define SMEM_CONV (4*1024*4 + 2*2048*4)        // 32768 B
#define SMEM_GEMM (4*2048*4 + 4*2048*4)        // 65536 B

extern "C" void kernel_launch(void* const* d_in, const int* in_sizes, int n_in,
                              void* d_out, int out_size)
{
    const float* x      = (const float*)d_in[0];
    const float* w_init = (const float*)d_in[1];
    const float* b_init = (const float*)d_in[2];
    const float* ln_cg  = (const float*)d_in[3];
    const float* ln_cb  = (const float*)d_in[4];
    const float* w_dw   = (const float*)d_in[5];
    const float* b_dw   = (const float*)d_in[6];
    const float* w_pw   = (const float*)d_in[7];
    const float* b_pw   = (const float*)d_in[8];
    const float* ln_ag  = (const float*)d_in[9];
    const float* ln_ab  = (const float*)d_in[10];
    const float* wq     = (const float*)d_in[11];
    const float* bq     = (const float*)d_in[12];
    const float* wk     = (const float*)d_in[13];
    const float* bk     = (const float*)d_in[14];
    const float* wv     = (const float*)d_in[15];
    const float* bv     = (const float*)d_in[16];
    const float* wo     = (const float*)d_in[17];
    const float* bo     = (const float*)d_in[18];
    const float* ln_fg  = (const float*)d_in[19];
    const float* ln_fb  = (const float*)d_in[20];
    const float* w1     = (const float*)d_in[21];
    const float* b1     = (const float*)d_in[22];
    const float* w2     = (const float*)d_in[23];
    const float* b2     = (const float*)d_in[24];

    float *xpad, *h, *ln, *tmp, *q, *k, *v, *att;
    uint32_t *bh, *bl;
    cudaGetSymbolAddress((void**)&xpad, g_xpad);
    cudaGetSymbolAddress((void**)&h,    g_h);
    cudaGetSymbolAddress((void**)&ln,   g_ln);
    cudaGetSymbolAddress((void**)&tmp,  g_tmp);
    cudaGetSymbolAddress((void**)&q,    g_q);
    cudaGetSymbolAddress((void**)&k,    g_k);
    cudaGetSymbolAddress((void**)&v,    g_v);
    cudaGetSymbolAddress((void**)&att,  g_att);
    cudaGetSymbolAddress((void**)&bh,   g_bh);
    cudaGetSymbolAddress((void**)&bl,   g_bl);

    cudaFuncSetAttribute(gemm_mma<64, CONV_CHUNKS, true, 2>,
        cudaFuncAttributeMaxDynamicSharedMemorySize, SMEM_CONV);
    cudaFuncSetAttribute(gemm_mma<128, GEMM_CHUNKS, false, 3>,
        cudaFuncAttributeMaxDynamicSharedMemorySize, SMEM_GEMM);

    // 1) pad x, posenc, weight prep
    pad_kernel<<<(BATCH*LPAD*(CIN/4) + 255)/256, 256>>>(x);
    pe_kernel<<<(LSEQ*DMODEL + 255)/256, 256>>>();
    prep_w_kernel<<<(CONV_BWORDS + 10*GEMM_BWORDS)/256, 256>>>(
        w_init, w_pw, wq, wk, wv, wo, w1, w2);

    // 2) init conv (implicit GEMM, fp16 2-pass, pipelined) + posenc -> h
    gemm_mma<64, CONV_CHUNKS, true, 2><<<MROWS/64, 256, SMEM_CONV>>>(
        xpad, bh, bl, b_init, nullptr, h, 0, 0);

    #define GW(m) (bh + CONV_BWORDS + (m)*GEMM_BWORDS), (bl + CONV_BWORDS + (m)*GEMM_BWORDS)

    // 3) 4x depthwise-separable conv blocks (fused ln+dw, then pw GEMM)
    for (int i = 0; i < 4; i++){
        lndw_kernel<<<BATCH*8, 256>>>(h, ln_cg + i*DMODEL, ln_cb + i*DMODEL,
                                      w_dw + i*7*DMODEL, b_dw + i*DMODEL, tmp);
        gemm_mma<128, GEMM_CHUNKS, false, 3><<<MROWS/128, 256, SMEM_GEMM>>>(
            tmp, GW(i), b_pw + i*DMODEL, h, h, 1, 1);
    }

    // 4) attention
    ln_kernel<<<MROWS/8, 256>>>(h, ln_ag, ln_ab, ln);
    gemm_mma<128, GEMM_CHUNKS, false, 3><<<MROWS/128, 256, SMEM_GEMM>>>(
        ln, GW(4), bq, nullptr, q, 0, 0);
    gemm_mma<128, GEMM_CHUNKS, false, 3><<<MROWS/128, 256, SMEM_GEMM>>>(
        ln, GW(5), bk, nullptr, k, 0, 0);
    gemm_mma<128, GEMM_CHUNKS, false, 3><<<MROWS/128, 256, SMEM_GEMM>>>(
        ln, GW(6), bv, nullptr, v, 0, 0);
    attn_kernel<<<BATCH*NHEAD, 416>>>(q, k, v, att);
    gemm_mma<128, GEMM_CHUNKS, false, 3><<<MROWS/128, 256, SMEM_GEMM>>>(
        att, GW(7), bo, h, tmp, 0, 1);

    // 5) FFN -> d_out
    ln_kernel<<<MROWS/8, 256>>>(tmp, ln_fg, ln_fb, ln);
    gemm_mma<128, GEMM_CHUNKS, false, 3><<<MROWS/128, 256, SMEM_GEMM>>>(
        ln, GW(8), b1, nullptr, q, 1, 0);
    gemm_mma<128, GEMM_CHUNKS, false, 3><<<MROWS/128, 256, SMEM_GEMM>>>(
        q, GW(9), b2, tmp, (float*)d_out, 0, 1);
}

// round 8
// speedup vs baseline: 2.2256x; 1.2419x over previous
#include <cuda_runtime.h>
#include <cuda_fp16.h>
#include <cstdint>

typedef unsigned long long ull;

// Problem constants
#define BATCH 64
#define LSEQ  400
#define CIN   500
#define DMODEL 128
#define NHEAD 8
#define HDIM  16
#define MROWS (BATCH*LSEQ)          // 25600
#define LPAD  (LSEQ+4)              // 404
#define KCONV 2500
#define CONV_CHUNKS 80              // K padded to 2560, BK=32
#define GEMM_CHUNKS 4               // K=128
#define CONV_BWORDS (CONV_CHUNKS*2048)
#define GEMM_BWORDS (GEMM_CHUNKS*2048)

// ---------------- scratch ----------------------------------------------------
__device__ __half g_xph[BATCH*LPAD*CIN + 4096];   // padded input, fp16 hi
__device__ __half g_xpl[BATCH*LPAD*CIN + 4096];   // fp16 lo
__device__ float g_pe[LSEQ*DMODEL];
__device__ float g_h  [MROWS*DMODEL];             // residual stream (fp32)
__device__ float g_tmp[MROWS*DMODEL];             // wo-out residual (fp32)
__device__ float g_q [MROWS*DMODEL];
__device__ float g_k [MROWS*DMODEL];
__device__ float g_v [MROWS*DMODEL];
// fp16-pair intermediates (half2-packed words, [MROWS][64])
__device__ uint32_t g_lnh[MROWS*64],  g_lnl[MROWS*64];
__device__ uint32_t g_dwh[MROWS*64],  g_dwl[MROWS*64];
__device__ uint32_t g_ath[MROWS*64],  g_atl[MROWS*64];
__device__ uint32_t g_ffh[MROWS*64],  g_ffl[MROWS*64];

// pre-split weights in HMMA B-fragment order, fp16x2 packed in u32
__device__ uint32_t g_bh[CONV_BWORDS + 10*GEMM_BWORDS];
__device__ uint32_t g_bl[CONV_BWORDS + 10*GEMM_BWORDS];

// ---------------- helpers ----------------------------------------------------
__device__ __forceinline__ uint32_t smem_u32(const void* p){
    uint32_t a;
    asm("{ .reg .u64 t; cvta.to.shared.u64 t, %1; cvt.u32.u64 %0, t; }"
        : "=r"(a) : "l"(p));
    return a;
}
__device__ __forceinline__ ull pack2f(float a){
    ull r; asm("mov.b64 %0, {%1, %1};" : "=l"(r) : "f"(a)); return r;
}
__device__ __forceinline__ void ffma2(ull& c, ull a, ull b){
    asm("fma.rn.f32x2 %0, %1, %2, %0;" : "+l"(c) : "l"(a), "l"(b));
}
__device__ __forceinline__ void split2(float f0, float f1, uint32_t& h, uint32_t& l){
    __half h0 = __float2half_rn(f0);
    __half h1 = __float2half_rn(f1);
    float r0 = f0 - __half2float(h0);
    float r1 = f1 - __half2float(h1);
    __half l0 = __float2half_rn(r0);
    __half l1 = __float2half_rn(r1);
    unsigned short hu0 = *(unsigned short*)&h0, hu1 = *(unsigned short*)&h1;
    unsigned short lu0 = *(unsigned short*)&l0, lu1 = *(unsigned short*)&l1;
    h = (uint32_t)hu0 | ((uint32_t)hu1 << 16);
    l = (uint32_t)lu0 | ((uint32_t)lu1 << 16);
}
__device__ __forceinline__ void mma_f16(float* d, const uint32_t* a, const uint32_t* b){
    asm volatile(
        "mma.sync.aligned.m16n8k16.row.col.f32.f16.f16.f32 "
        "{%0,%1,%2,%3}, {%4,%5,%6,%7}, {%8,%9}, {%0,%1,%2,%3};"
        : "+f"(d[0]), "+f"(d[1]), "+f"(d[2]), "+f"(d[3])
        : "r"(a[0]), "r"(a[1]), "r"(a[2]), "r"(a[3]), "r"(b[0]), "r"(b[1]));
}
__device__ __forceinline__ void ldm_x4(uint32_t* r, uint32_t addr){
    asm volatile("ldmatrix.sync.aligned.m8n8.x4.shared.b16 {%0,%1,%2,%3}, [%4];"
        : "=r"(r[0]), "=r"(r[1]), "=r"(r[2]), "=r"(r[3]) : "r"(addr));
}
__device__ __forceinline__ void cp16(uint32_t daddr, const void* gptr){
    asm volatile("cp.async.cg.shared.global [%0], [%1], 16;"
                 :: "r"(daddr), "l"(gptr) : "memory");
}
__device__ __forceinline__ void cp8(uint32_t daddr, const void* gptr){
    asm volatile("cp.async.ca.shared.global [%0], [%1], 8;"
                 :: "r"(daddr), "l"(gptr) : "memory");
}
__device__ __forceinline__ void cp_commit(){
    asm volatile("cp.async.commit_group;" ::: "memory");
}
__device__ __forceinline__ void cp_wait0(){
    asm volatile("cp.async.wait_group 0;" ::: "memory");
}

// ---------------- pad x -> fp16 hi/lo planes [B,404,500] ---------------------
__global__ void __launch_bounds__(256) pad_kernel(const float* __restrict__ x){
    int idx = blockIdx.x*256 + threadIdx.x;
    if (idx >= BATCH*LPAD*(CIN/4)) return;
    int c4 = idx % (CIN/4);
    int rest = idx / (CIN/4);
    int lp = rest % LPAD;
    int b  = rest / LPAD;
    int l = lp - 2;
    float4 v = make_float4(0.f,0.f,0.f,0.f);
    if (l >= 0 && l < LSEQ) v = ((const float4*)x)[(b*LSEQ + l)*(CIN/4) + c4];
    uint32_t h0,l0,h1,l1;
    split2(v.x, v.y, h0, l0);
    split2(v.z, v.w, h1, l1);
    long u2 = (long)rest*125 + c4;           // uint2 index: row*1000B/8 + c4
    ((uint2*)g_xph)[u2] = make_uint2(h0, h1);
    ((uint2*)g_xpl)[u2] = make_uint2(l0, l1);
}

// ---------------- positional encoding table ---------------------------------
__global__ void __launch_bounds__(256) pe_kernel(){
    int idx = blockIdx.x*256 + threadIdx.x;
    if (idx >= LSEQ*DMODEL) return;
    int l = idx / DMODEL;
    int d = idx % DMODEL;
    int j = d & ~1;
    float div = expf(-(float)j * (logf(10000.f)/(float)DMODEL));
    float ang = (float)l * div;
    g_pe[idx] = (d & 1) ? cosf(ang) : sinf(ang);
}

// ---------------- weight prep into HMMA B-fragment order (fp16 hi/lo) --------
__global__ void __launch_bounds__(256) prep_w_kernel(
    const float* __restrict__ w_init, const float* __restrict__ w_pw,
    const float* __restrict__ wq, const float* __restrict__ wk,
    const float* __restrict__ wv, const float* __restrict__ wo,
    const float* __restrict__ w1, const float* __restrict__ w2)
{
    int flat = blockIdx.x*256 + threadIdx.x;
    const float* W; int K, ch, w2i;
    if (flat < CONV_BWORDS){
        W = w_init; K = KCONV;
        ch = flat >> 11; w2i = flat & 2047;
    } else {
        int rem = flat - CONV_BWORDS;
        int m = rem >> 13;
        int w2g = rem & 8191;
        ch = w2g >> 11; w2i = w2g & 2047;
        K = DMODEL;
        switch (m){
            case 0: case 1: case 2: case 3: W = w_pw + m*DMODEL*DMODEL; break;
            case 4: W = wq; break; case 5: W = wk; break;
            case 6: W = wv; break; case 7: W = wo; break;
            case 8: W = w1; break; default: W = w2; break;
        }
    }
    int j    = w2i & 1;
    int lane = (w2i >> 1) & 31;
    int snt  = w2i >> 6;
    int nt   = snt & 15;
    int s    = snt >> 4;
    int n  = nt*8 + (lane >> 2);
    int k2 = (lane & 3) + j*4 + s*8 + ch*16;
    int k  = 2*k2;
    float v0 = (k   < K) ? W[(long)k    *DMODEL + n] : 0.f;
    float v1 = (k+1 < K) ? W[(long)(k+1)*DMODEL + n] : 0.f;
    uint32_t h, l;
    split2(v0, v1, h, l);
    g_bh[flat] = h;
    g_bl[flat] = l;
}

// ---------------- pipelined HMMA fp16 GEMM (pre-split A, ldmatrix) -----------
// BM=64, 256 threads. A planes row-linear in smem, 80B row stride (bank-clean).
// PASSES=2: Ah*Bh + Al*Bh (conv); PASSES=3: + Ah*Bl.
template<int KCHUNKS, bool CONV, int PASSES, bool OUTF16>
__global__ void __launch_bounds__(256) gemm_mma(
    const __half* __restrict__ Ah, const __half* __restrict__ Al,
    const uint32_t* __restrict__ Bhi, const uint32_t* __restrict__ Blo,
    const float* __restrict__ bias, const float* __restrict__ res,
    float* __restrict__ C, uint32_t* __restrict__ Ch, uint32_t* __restrict__ Cl,
    int relu_flag, int res_flag)
{
    constexpr int ABYTES = 64*80;            // one plane, one stage
    constexpr int NPB = (PASSES == 3) ? 2 : 1;
    constexpr int AOFF_TOT = 4*ABYTES;       // 2 stages x 2 planes

    extern __shared__ char smem[];
    uint32_t aBase = smem_u32(smem);
    uint32_t bBase = aBase + AOFF_TOT;
    char* bPtr = smem + AOFF_TOT;

    int t = threadIdx.x, lane = t & 31, wid = t >> 5;
    int m0 = blockIdx.x * 64;
    int wm = wid & 1, wn = wid >> 1;         // 2 x 4 warp grid

    // A global bases
    long abaseC[2]; int u8 = t & 7; int r0 = t >> 3;
    if (CONV){
        #pragma unroll
        for (int i = 0; i < 2; i++){
            int m = m0 + r0 + i*32; int b = m / LSEQ; int l = m - b*LSEQ;
            abaseC[i] = (long)(b*LPAD + l) * CIN;
        }
    }
    long abaseD = (long)(m0 + (t >> 2)) * DMODEL;

    float d[2][4][4];
    #pragma unroll
    for (int a=0;a<2;a++)
        #pragma unroll
        for (int b=0;b<4;b++)
            #pragma unroll
            for (int c=0;c<4;c++) d[a][b][c] = 0.f;

    // ldmatrix per-lane addressing
    int rowl = lane & 15, ksel = lane >> 4;

    // ---- loader lambda-ish macro ----
    auto load_chunk = [&](int ch, int stage){
        if (CONV){
            #pragma unroll
            for (int i = 0; i < 4; i++){
                const __half* P = (i < 2) ? Ah : Al;
                int rsel = i & 1;
                uint32_t dst = aBase + (uint32_t)(stage*2 + (i>>1))*ABYTES
                             + (uint32_t)(r0 + rsel*32)*80 + u8*8;
                cp8(dst, P + abaseC[rsel] + ch*32 + u8*4);
            }
        } else {
            #pragma unroll
            for (int i = 0; i < 2; i++){
                const __half* P = i ? Al : Ah;
                uint32_t dst = aBase + (uint32_t)(stage*2 + i)*ABYTES
                             + (uint32_t)(t>>2)*80 + (t&3)*16;
                cp16(dst, P + abaseD + ch*32 + (t&3)*8);
            }
        }
        {
            const uint4* gh = (const uint4*)(Bhi + (long)ch*2048);
            uint32_t dst = bBase + (uint32_t)stage*NPB*8192;
            cp16(dst + (uint32_t)t*16,       gh + t);
            cp16(dst + (uint32_t)(t+256)*16, gh + t + 256);
            if (PASSES == 3){
                const uint4* gl = (const uint4*)(Blo + (long)ch*2048);
                uint32_t dstl = dst + 8192;
                cp16(dstl + (uint32_t)t*16,       gl + t);
                cp16(dstl + (uint32_t)(t+256)*16, gl + t + 256);
            }
        }
        cp_commit();
    };

    load_chunk(0, 0);

    for (int ch = 0; ch < KCHUNKS; ch++){
        int cur = ch & 1;
        cp_wait0();
        __syncthreads();
        if (ch + 1 < KCHUNKS) load_chunk(ch + 1, cur ^ 1);

        const char* bStage = bPtr + (long)cur*NPB*8192;
        #pragma unroll
        for (int s = 0; s < 2; s++){
            uint32_t ah[2][4], al[2][4];
            #pragma unroll
            for (int mt2 = 0; mt2 < 2; mt2++){
                int mt = wm*2 + mt2;
                uint32_t aaddr = aBase + (uint32_t)(cur*2)*ABYTES
                               + (uint32_t)(mt*16 + rowl)*80 + (s*2 + ksel)*16;
                ldm_x4(ah[mt2], aaddr);
                ldm_x4(al[mt2], aaddr + ABYTES);
            }
            #pragma unroll
            for (int nt = 0; nt < 4; nt++){
                int ntg = wn*4 + nt;
                uint2 bh = *(const uint2*)(bStage + ((s*16 + ntg)*32 + lane)*8);
                #pragma unroll
                for (int mt2 = 0; mt2 < 2; mt2++){
                    mma_f16(d[mt2][nt], ah[mt2], (const uint32_t*)&bh);
                    mma_f16(d[mt2][nt], al[mt2], (const uint32_t*)&bh);
                }
                if (PASSES == 3){
                    uint2 bl = *(const uint2*)(bStage + 8192 + ((s*16 + ntg)*32 + lane)*8);
                    #pragma unroll
                    for (int mt2 = 0; mt2 < 2; mt2++)
                        mma_f16(d[mt2][nt], ah[mt2], (const uint32_t*)&bl);
                }
            }
        }
    }

    // epilogue
    int g = lane >> 2, t_ = lane & 3;
    #pragma unroll
    for (int mt2 = 0; mt2 < 2; mt2++){
        int rbase = m0 + wm*32 + mt2*16 + g;
        #pragma unroll
        for (int hf = 0; hf < 2; hf++){
            int row = rbase + hf*8;
            const float* pe = CONV ? (g_pe + (long)(row % LSEQ)*DMODEL) : (const float*)0;
            #pragma unroll
            for (int nt = 0; nt < 4; nt++){
                int col = wn*32 + nt*8 + t_*2;
                float v0 = d[mt2][nt][hf*2+0];
                float v1 = d[mt2][nt][hf*2+1];
                float2 bb = *(const float2*)(bias + col);
                v0 += bb.x; v1 += bb.y;
                if (CONV){
                    float2 p = *(const float2*)(pe + col);
                    v0 += p.x; v1 += p.y;
                }
                if (relu_flag){ v0 = fmaxf(v0, 0.f); v1 = fmaxf(v1, 0.f); }
                if (res_flag){
                    float2 r = *(const float2*)(res + (long)row*DMODEL + col);
                    v0 += r.x; v1 += r.y;
                }
                if (OUTF16){
                    uint32_t hh, ll;
                    split2(v0, v1, hh, ll);
                    long oi = (long)row*64 + (col >> 1);
                    Ch[oi] = hh; Cl[oi] = ll;
                } else {
                    *(float2*)(C + (long)row*DMODEL + col) = make_float2(v0, v1);
                }
            }
        }
    }
}

// ---------------- layernorm: one warp per row -> fp16 pair -------------------
__global__ void __launch_bounds__(256) ln_kernel(
    const float* __restrict__ x, const float* __restrict__ g,
    const float* __restrict__ b, uint32_t* __restrict__ yh,
    uint32_t* __restrict__ yl)
{
    int t = threadIdx.x;
    int row = blockIdx.x*8 + (t >> 5);
    int lane = t & 31;
    float4 v = ((const float4*)x)[row*32 + lane];
    float s  = v.x + v.y + v.z + v.w;
    float sq = v.x*v.x + v.y*v.y + v.z*v.z + v.w*v.w;
    #pragma unroll
    for (int o = 16; o; o >>= 1){
        s  += __shfl_xor_sync(0xffffffffu, s,  o);
        sq += __shfl_xor_sync(0xffffffffu, sq, o);
    }
    float mean = s * (1.f/DMODEL);
    float var  = sq * (1.f/DMODEL) - mean*mean;
    float rs = rsqrtf(var + 1e-5f);
    float4 gg = ((const float4*)g)[lane];
    float4 bb = ((const float4*)b)[lane];
    float o0 = (v.x-mean)*rs*gg.x + bb.x;
    float o1 = (v.y-mean)*rs*gg.y + bb.y;
    float o2 = (v.z-mean)*rs*gg.z + bb.z;
    float o3 = (v.w-mean)*rs*gg.w + bb.w;
    uint32_t h0,l0,h1,l1;
    split2(o0,o1,h0,l0); split2(o2,o3,h1,l1);
    ((uint2*)yh)[row*32 + lane] = make_uint2(h0,h1);
    ((uint2*)yl)[row*32 + lane] = make_uint2(l0,l1);
}

// ---------------- fused layernorm + depthwise conv k=7 -> fp16 pair ----------
__global__ void __launch_bounds__(256) lndw_kernel(
    const float* __restrict__ x, const float* __restrict__ g,
    const float* __restrict__ b, const float* __restrict__ wdw,
    const float* __restrict__ bdw, uint32_t* __restrict__ yh,
    uint32_t* __restrict__ yl)
{
    __shared__ float4 sln[56][32];
    int blk = blockIdx.x;
    int bidx = blk >> 3, lb = blk & 7;
    int l0 = lb * 50;
    int t = threadIdx.x, wid = t >> 5, lane = t & 31;

    float4 gg = ((const float4*)g)[lane];
    float4 bb = ((const float4*)b)[lane];

    #pragma unroll
    for (int rr = 0; rr < 7; rr++){
        int r = wid + rr*8;
        int l = l0 - 3 + r;
        float4 o4 = make_float4(0.f,0.f,0.f,0.f);
        if (l >= 0 && l < LSEQ){
            float4 v = ((const float4*)x)[(bidx*LSEQ + l)*32 + lane];
            float s  = v.x + v.y + v.z + v.w;
            float sq = v.x*v.x + v.y*v.y + v.z*v.z + v.w*v.w;
            #pragma unroll
            for (int o = 16; o; o >>= 1){
                s  += __shfl_xor_sync(0xffffffffu, s,  o);
                sq += __shfl_xor_sync(0xffffffffu, sq, o);
            }
            float mean = s * (1.f/DMODEL);
            float var  = sq * (1.f/DMODEL) - mean*mean;
            float rs = rsqrtf(var + 1e-5f);
            o4.x = (v.x-mean)*rs*gg.x + bb.x;
            o4.y = (v.y-mean)*rs*gg.y + bb.y;
            o4.z = (v.z-mean)*rs*gg.z + bb.z;
            o4.w = (v.w-mean)*rs*gg.w + bb.w;
        }
        sln[r][lane] = o4;
    }
    __syncthreads();

    float4 wv[7];
    #pragma unroll
    for (int tap = 0; tap < 7; tap++) wv[tap] = ((const float4*)wdw)[tap*32 + lane];
    float4 bias4 = ((const float4*)bdw)[lane];

    #pragma unroll
    for (int rr = 0; rr < 7; rr++){
        int r = wid + rr*8;
        if (r < 50){
            float4 acc = bias4;
            #pragma unroll
            for (int tap = 0; tap < 7; tap++){
                float4 xv = sln[r + tap][lane];
                acc.x += xv.x*wv[tap].x; acc.y += xv.y*wv[tap].y;
                acc.z += xv.z*wv[tap].z; acc.w += xv.w*wv[tap].w;
            }
            uint32_t h0,lo0,h1,lo1;
            split2(acc.x,acc.y,h0,lo0); split2(acc.z,acc.w,h1,lo1);
            long u2 = (long)(bidx*LSEQ + l0 + r)*32 + lane;
            ((uint2*)yh)[u2] = make_uint2(h0,h1);
            ((uint2*)yl)[u2] = make_uint2(lo0,lo1);
        }
    }
}

// ---------------- attention: single-pass, fp16-pair output -------------------
#define JT 100
__global__ void __launch_bounds__(416) attn_kernel(
    const float* __restrict__ Q, const float* __restrict__ K,
    const float* __restrict__ V, uint32_t* __restrict__ Oh,
    uint32_t* __restrict__ Ol)
{
    __shared__ float2 Ks[JT][8];
    __shared__ float2 Vs[JT][8];
    int bh = blockIdx.x;
    int b = bh >> 3, hd = bh & 7;
    int i = threadIdx.x;

    ull q2[8];
    if (i < LSEQ){
        const ull* qp = (const ull*)(Q + (b*LSEQ + i)*DMODEL + hd*HDIM);
        #pragma unroll
        for (int p = 0; p < 8; p++) q2[p] = qp[p];
    }
    float ssum = 0.f;
    ull o2[8];
    #pragma unroll
    for (int p = 0; p < 8; p++) o2[p] = 0ull;

    for (int jt = 0; jt < 4; jt++){
        __syncthreads();
        for (int idx = threadIdx.x; idx < JT*8; idx += 416){
            int jj = idx >> 3, hd2 = idx & 7;
            int gidx = (b*LSEQ + jt*JT + jj)*(DMODEL/2) + hd*8 + hd2;
            Ks[jj][hd2] = ((const float2*)K)[gidx];
            Vs[jj][hd2] = ((const float2*)V)[gidx];
        }
        __syncthreads();
        if (i < LSEQ){
            for (int jj = 0; jj < JT; jj++){
                ull acc = 0ull;
                const ull* kp = (const ull*)&Ks[jj][0];
                #pragma unroll
                for (int p = 0; p < 8; p++) ffma2(acc, q2[p], kp[p]);
                float2 af = *(float2*)&acc;
                float s = (af.x + af.y) * 0.25f;
                float pv = __expf(s);
                ssum += pv;
                ull p2 = pack2f(pv);
                const ull* vp = (const ull*)&Vs[jj][0];
                #pragma unroll
                for (int p = 0; p < 8; p++) ffma2(o2[p], p2, vp[p]);
            }
        }
    }
    if (i < LSEQ){
        float inv = 1.f / ssum;
        long obase = (long)(b*LSEQ + i)*64 + hd*8;
        #pragma unroll
        for (int p = 0; p < 8; p++){
            float2 f = *(float2*)&o2[p];
            uint32_t hh, ll;
            split2(f.x*inv, f.y*inv, hh, ll);
            Oh[obase + p] = hh;
            Ol[obase + p] = ll;
        }
    }
}

// ---------------- host orchestration ----------------------------------------
#define SMEM_CONV (4*64*80 + 2*8192)       // 36864 B
#define SMEM_GEMM (4*64*80 + 4*8192)       // 53248 B

extern "C" void kernel_launch(void* const* d_in, const int* in_sizes, int n_in,
                              void* d_out, int out_size)
{
    const float* x      = (const float*)d_in[0];
    const float* w_init = (const float*)d_in[1];
    const float* b_init = (const float*)d_in[2];
    const float* ln_cg  = (const float*)d_in[3];
    const float* ln_cb  = (const float*)d_in[4];
    const float* w_dw   = (const float*)d_in[5];
    const float* b_dw   = (const float*)d_in[6];
    const float* w_pw   = (const float*)d_in[7];
    const float* b_pw   = (const float*)d_in[8];
    const float* ln_ag  = (const float*)d_in[9];
    const float* ln_ab  = (const float*)d_in[10];
    const float* wq     = (const float*)d_in[11];
    const float* bq     = (const float*)d_in[12];
    const float* wk     = (const float*)d_in[13];
    const float* bk     = (const float*)d_in[14];
    const float* wv     = (const float*)d_in[15];
    const float* bv     = (const float*)d_in[16];
    const float* wo     = (const float*)d_in[17];
    const float* bo     = (const float*)d_in[18];
    const float* ln_fg  = (const float*)d_in[19];
    const float* ln_fb  = (const float*)d_in[20];
    const float* w1     = (const float*)d_in[21];
    const float* b1     = (const float*)d_in[22];
    const float* w2     = (const float*)d_in[23];
    const float* b2     = (const float*)d_in[24];

    __half *xph, *xpl;
    float *h, *tmp, *q, *k, *v;
    uint32_t *lnh, *lnl, *dwh, *dwl, *ath, *atl, *ffh, *ffl, *bh, *bl;
    cudaGetSymbolAddress((void**)&xph, g_xph);
    cudaGetSymbolAddress((void**)&xpl, g_xpl);
    cudaGetSymbolAddress((void**)&h,   g_h);
    cudaGetSymbolAddress((void**)&tmp, g_tmp);
    cudaGetSymbolAddress((void**)&q,   g_q);
    cudaGetSymbolAddress((void**)&k,   g_k);
    cudaGetSymbolAddress((void**)&v,   g_v);
    cudaGetSymbolAddress((void**)&lnh, g_lnh);
    cudaGetSymbolAddress((void**)&lnl, g_lnl);
    cudaGetSymbolAddress((void**)&dwh, g_dwh);
    cudaGetSymbolAddress((void**)&dwl, g_dwl);
    cudaGetSymbolAddress((void**)&ath, g_ath);
    cudaGetSymbolAddress((void**)&atl, g_atl);
    cudaGetSymbolAddress((void**)&ffh, g_ffh);
    cudaGetSymbolAddress((void**)&ffl, g_ffl);
    cudaGetSymbolAddress((void**)&bh,  g_bh);
    cudaGetSymbolAddress((void**)&bl,  g_bl);

    cudaFuncSetAttribute(gemm_mma<CONV_CHUNKS, true, 2, false>,
        cudaFuncAttributeMaxDynamicSharedMemorySize, SMEM_CONV);
    cudaFuncSetAttribute(gemm_mma<GEMM_CHUNKS, false, 3, false>,
        cudaFuncAttributeMaxDynamicSharedMemorySize, SMEM_GEMM);
    cudaFuncSetAttribute(gemm_mma<GEMM_CHUNKS, false, 3, true>,
        cudaFuncAttributeMaxDynamicSharedMemorySize, SMEM_GEMM);

    // 1) pad+split x, posenc, weight prep
    pad_kernel<<<(BATCH*LPAD*(CIN/4) + 255)/256, 256>>>(x);
    pe_kernel<<<(LSEQ*DMODEL + 255)/256, 256>>>();
    prep_w_kernel<<<(CONV_BWORDS + 10*GEMM_BWORDS)/256, 256>>>(
        w_init, w_pw, wq, wk, wv, wo, w1, w2);

    // 2) init conv (implicit GEMM) + posenc -> h
    gemm_mma<CONV_CHUNKS, true, 2, false><<<MROWS/64, 256, SMEM_CONV>>>(
        xph, xpl, bh, bl, b_init, nullptr, h, nullptr, nullptr, 0, 0);

    #define GW(m) (bh + CONV_BWORDS + (m)*GEMM_BWORDS), (bl + CONV_BWORDS + (m)*GEMM_BWORDS)

    // 3) 4x depthwise-separable conv blocks
    for (int i = 0; i < 4; i++){
        lndw_kernel<<<BATCH*8, 256>>>(h, ln_cg + i*DMODEL, ln_cb + i*DMODEL,
                                      w_dw + i*7*DMODEL, b_dw + i*DMODEL, dwh, dwl);
        gemm_mma<GEMM_CHUNKS, false, 3, false><<<MROWS/64, 256, SMEM_GEMM>>>(
            (const __half*)dwh, (const __half*)dwl, GW(i),
            b_pw + i*DMODEL, h, h, nullptr, nullptr, 1, 1);
    }

    // 4) attention
    ln_kernel<<<MROWS/8, 256>>>(h, ln_ag, ln_ab, lnh, lnl);
    gemm_mma<GEMM_CHUNKS, false, 3, false><<<MROWS/64, 256, SMEM_GEMM>>>(
        (const __half*)lnh, (const __half*)lnl, GW(4), bq, nullptr, q, nullptr, nullptr, 0, 0);
    gemm_mma<GEMM_CHUNKS, false, 3, false><<<MROWS/64, 256, SMEM_GEMM>>>(
        (const __half*)lnh, (const __half*)lnl, GW(5), bk, nullptr, k, nullptr, nullptr, 0, 0);
    gemm_mma<GEMM_CHUNKS, false, 3, false><<<MROWS/64, 256, SMEM_GEMM>>>(
        (const __half*)lnh, (const __half*)lnl, GW(6), bv, nullptr, v, nullptr, nullptr, 0, 0);
    attn_kernel<<<BATCH*NHEAD, 416>>>(q, k, v, ath, atl);
    gemm_mma<GEMM_CHUNKS, false, 3, false><<<MROWS/64, 256, SMEM_GEMM>>>(
        (const __half*)ath, (const __half*)atl, GW(7), bo, h, tmp, nullptr, nullptr, 0, 1);

    // 5) FFN -> d_out
    ln_kernel<<<MROWS/8, 256>>>(tmp, ln_fg, ln_fb, lnh, lnl);
    gemm_mma<GEMM_CHUNKS, false, 3, true><<<MROWS/64, 256, SMEM_GEMM>>>(
        (const __half*)lnh, (const __half*)lnl, GW(8), b1, nullptr, nullptr, ffh, ffl, 1, 0);
    gemm_mma<GEMM_CHUNKS, false, 3, false><<<MROWS/64, 256, SMEM_GEMM>>>(
        (const __half*)ffh, (const __half*)ffl, GW(9), b2, tmp, (float*)d_out, nullptr, nullptr, 0, 1);
}

// round 12
// speedup vs baseline: 2.5117x; 1.1286x over previous
#include <cuda_runtime.h>
#include <cuda_fp16.h>
#include <cstdint>

typedef unsigned long long ull;

// Problem constants
#define BATCH 64
#define LSEQ  400
#define CIN   500
#define DMODEL 128
#define NHEAD 8
#define HDIM  16
#define MROWS (BATCH*LSEQ)          // 25600
#define LPAD  (LSEQ+4)              // 404
#define KCONV 2500
#define CONV_CHUNKS 80              // K padded to 2560, BK=32
#define GEMM_CHUNKS 4               // K=128
#define CONV_BWORDS (CONV_CHUNKS*2048)
#define GEMM_BWORDS (GEMM_CHUNKS*2048)

// ---------------- scratch ----------------------------------------------------
__device__ __half g_xph[BATCH*LPAD*CIN + 4096];   // padded input, fp16 hi only
__device__ float g_pe[LSEQ*DMODEL];
__device__ float g_h  [MROWS*DMODEL];             // residual stream (fp32)
__device__ float g_tmp[MROWS*DMODEL];
__device__ float g_q [MROWS*DMODEL];
__device__ float g_k [MROWS*DMODEL];
__device__ float g_v [MROWS*DMODEL];
// fp16-pair intermediates (half2-packed words, [MROWS][64])
__device__ uint32_t g_lnh[MROWS*64],  g_lnl[MROWS*64];
__device__ uint32_t g_dwh[MROWS*64],  g_dwl[MROWS*64];
__device__ uint32_t g_ath[MROWS*64],  g_atl[MROWS*64];
__device__ uint32_t g_ffh[MROWS*64],  g_ffl[MROWS*64];

// pre-split weights in HMMA B-fragment order, fp16x2 words (hi plane only)
__device__ uint32_t g_bh[CONV_BWORDS + 10*GEMM_BWORDS];

// ---------------- helpers ----------------------------------------------------
__device__ __forceinline__ uint32_t smem_u32(const void* p){
    uint32_t a;
    asm("{ .reg .u64 t; cvta.to.shared.u64 t, %1; cvt.u32.u64 %0, t; }"
        : "=r"(a) : "l"(p));
    return a;
}
__device__ __forceinline__ ull pack2f(float a){
    ull r; asm("mov.b64 %0, {%1, %1};" : "=l"(r) : "f"(a)); return r;
}
__device__ __forceinline__ void ffma2(ull& c, ull a, ull b){
    asm("fma.rn.f32x2 %0, %1, %2, %0;" : "+l"(c) : "l"(a), "l"(b));
}
__device__ __forceinline__ void split2(float f0, float f1, uint32_t& h, uint32_t& l){
    __half h0 = __float2half_rn(f0);
    __half h1 = __float2half_rn(f1);
    float r0 = f0 - __half2float(h0);
    float r1 = f1 - __half2float(h1);
    __half l0 = __float2half_rn(r0);
    __half l1 = __float2half_rn(r1);
    unsigned short hu0 = *(unsigned short*)&h0, hu1 = *(unsigned short*)&h1;
    unsigned short lu0 = *(unsigned short*)&l0, lu1 = *(unsigned short*)&l1;
    h = (uint32_t)hu0 | ((uint32_t)hu1 << 16);
    l = (uint32_t)lu0 | ((uint32_t)lu1 << 16);
}
__device__ __forceinline__ uint32_t pack_hi2(float f0, float f1){
    __half h0 = __float2half_rn(f0);
    __half h1 = __float2half_rn(f1);
    unsigned short hu0 = *(unsigned short*)&h0, hu1 = *(unsigned short*)&h1;
    return (uint32_t)hu0 | ((uint32_t)hu1 << 16);
}
__device__ __forceinline__ void mma_f16(float* d, const uint32_t* a, const uint32_t* b){
    asm volatile(
        "mma.sync.aligned.m16n8k16.row.col.f32.f16.f16.f32 "
        "{%0,%1,%2,%3}, {%4,%5,%6,%7}, {%8,%9}, {%0,%1,%2,%3};"
        : "+f"(d[0]), "+f"(d[1]), "+f"(d[2]), "+f"(d[3])
        : "r"(a[0]), "r"(a[1]), "r"(a[2]), "r"(a[3]), "r"(b[0]), "r"(b[1]));
}
__device__ __forceinline__ void ldm_x4(uint32_t* r, uint32_t addr){
    asm volatile("ldmatrix.sync.aligned.m8n8.x4.shared.b16 {%0,%1,%2,%3}, [%4];"
        : "=r"(r[0]), "=r"(r[1]), "=r"(r[2]), "=r"(r[3]) : "r"(addr));
}
__device__ __forceinline__ void cp16(uint32_t daddr, const void* gptr){
    asm volatile("cp.async.cg.shared.global [%0], [%1], 16;"
                 :: "r"(daddr), "l"(gptr) : "memory");
}
__device__ __forceinline__ void cp8(uint32_t daddr, const void* gptr){
    asm volatile("cp.async.ca.shared.global [%0], [%1], 8;"
                 :: "r"(daddr), "l"(gptr) : "memory");
}
__device__ __forceinline__ void cp_commit(){
    asm volatile("cp.async.commit_group;" ::: "memory");
}
__device__ __forceinline__ void cp_wait0(){
    asm volatile("cp.async.wait_group 0;" ::: "memory");
}

// ---------------- pad x -> fp16 hi plane [B,404,500] -------------------------
__global__ void __launch_bounds__(256) pad_kernel(const float* __restrict__ x){
    int idx = blockIdx.x*256 + threadIdx.x;
    if (idx >= BATCH*LPAD*(CIN/4)) return;
    int c4 = idx % (CIN/4);
    int rest = idx / (CIN/4);
    int lp = rest % LPAD;
    int b  = rest / LPAD;
    int l = lp - 2;
    float4 v = make_float4(0.f,0.f,0.f,0.f);
    if (l >= 0 && l < LSEQ) v = ((const float4*)x)[(b*LSEQ + l)*(CIN/4) + c4];
    uint32_t h0 = pack_hi2(v.x, v.y);
    uint32_t h1 = pack_hi2(v.z, v.w);
    long u2 = (long)rest*125 + c4;
    ((uint2*)g_xph)[u2] = make_uint2(h0, h1);
}

// ---------------- positional encoding table ---------------------------------
__global__ void __launch_bounds__(256) pe_kernel(){
    int idx = blockIdx.x*256 + threadIdx.x;
    if (idx >= LSEQ*DMODEL) return;
    int l = idx / DMODEL;
    int d = idx % DMODEL;
    int j = d & ~1;
    float div = expf(-(float)j * (logf(10000.f)/(float)DMODEL));
    float ang = (float)l * div;
    g_pe[idx] = (d & 1) ? cosf(ang) : sinf(ang);
}

// ---------------- weight prep into HMMA B-fragment order (fp16 hi) -----------
__global__ void __launch_bounds__(256) prep_w_kernel(
    const float* __restrict__ w_init, const float* __restrict__ w_pw,
    const float* __restrict__ wq, const float* __restrict__ wk,
    const float* __restrict__ wv, const float* __restrict__ wo,
    const float* __restrict__ w1, const float* __restrict__ w2)
{
    int flat = blockIdx.x*256 + threadIdx.x;
    const float* W; int K, ch, w2i;
    if (flat < CONV_BWORDS){
        W = w_init; K = KCONV;
        ch = flat >> 11; w2i = flat & 2047;
    } else {
        int rem = flat - CONV_BWORDS;
        int m = rem >> 13;
        int w2g = rem & 8191;
        ch = w2g >> 11; w2i = w2g & 2047;
        K = DMODEL;
        switch (m){
            case 0: case 1: case 2: case 3: W = w_pw + m*DMODEL*DMODEL; break;
            case 4: W = wq; break; case 5: W = wk; break;
            case 6: W = wv; break; case 7: W = wo; break;
            case 8: W = w1; break; default: W = w2; break;
        }
    }
    int j    = w2i & 1;
    int lane = (w2i >> 1) & 31;
    int snt  = w2i >> 6;
    int nt   = snt & 15;
    int s    = snt >> 4;
    int n  = nt*8 + (lane >> 2);
    int k2 = (lane & 3) + j*4 + s*8 + ch*16;
    int k  = 2*k2;
    float v0 = (k   < K) ? W[(long)k    *DMODEL + n] : 0.f;
    float v1 = (k+1 < K) ? W[(long)(k+1)*DMODEL + n] : 0.f;
    g_bh[flat] = pack_hi2(v0, v1);
}

// ---------------- pipelined HMMA fp16 GEMM -----------------------------------
// BM=64, 256 threads, B hi only.
// NPA=1 (conv): Ah*Bh.  NPA=2 (dense): Ah*Bh + Al*Bh (A exact, B fp16-quantized)
// CONV A rows have 1000B stride (im2col contiguity) -> only 8B-aligned: use cp8.
template<int KCHUNKS, bool CONV, int NPA, bool OUTF16>
__global__ void __launch_bounds__(256) gemm_mma(
    const __half* __restrict__ Ah, const __half* __restrict__ Al,
    const uint32_t* __restrict__ Bhi,
    const float* __restrict__ bias, const float* __restrict__ res,
    float* __restrict__ C, uint32_t* __restrict__ Ch, uint32_t* __restrict__ Cl,
    int relu_flag, int res_flag)
{
    constexpr int ABYTES = 64*80;      // one plane, one stage (80B row stride)
    constexpr int AOFF_TOT = 2*NPA*ABYTES;

    extern __shared__ char smem[];
    uint32_t aBase = smem_u32(smem);
    uint32_t bBase = aBase + AOFF_TOT;
    char* bPtr = smem + AOFF_TOT;

    int t = threadIdx.x, lane = t & 31, wid = t >> 5;
    int m0 = blockIdx.x * 64;
    int wm = wid & 1, wn = wid >> 1;         // 2 x 4 warp grid

    // A global base: 4 threads per row, 16B each
    int arow = t >> 2, aq = t & 3;
    long abase;
    if (CONV){
        int m = m0 + arow; int b = m / LSEQ; int l = m - b*LSEQ;
        abase = (long)(b*LPAD + l) * CIN;
    } else {
        abase = (long)(m0 + arow) * DMODEL;
    }
    uint32_t aDstRow = (uint32_t)arow*80 + (uint32_t)aq*16;

    float d[2][4][4];
    #pragma unroll
    for (int a=0;a<2;a++)
        #pragma unroll
        for (int b=0;b<4;b++)
            #pragma unroll
            for (int c=0;c<4;c++) d[a][b][c] = 0.f;

    int rowl = lane & 15, ksel = lane >> 4;

    auto load_chunk = [&](int ch, int stage){
        if (CONV){
            // 1000B row stride -> 8B alignment only: two cp8 per thread
            const char* gp = (const char*)(Ah + abase + ch*32 + aq*8);
            uint32_t dst = aBase + (uint32_t)(stage*NPA)*ABYTES + aDstRow;
            cp8(dst,     gp);
            cp8(dst + 8, gp + 8);
        } else {
            cp16(aBase + (uint32_t)(stage*NPA)*ABYTES + aDstRow,
                 Ah + abase + ch*32 + aq*8);
            if (NPA == 2)
                cp16(aBase + (uint32_t)(stage*NPA + 1)*ABYTES + aDstRow,
                     Al + abase + ch*32 + aq*8);
        }
        const uint4* gh = (const uint4*)(Bhi + (long)ch*2048);
        uint32_t dst = bBase + (uint32_t)stage*8192;
        cp16(dst + (uint32_t)t*16,       gh + t);
        cp16(dst + (uint32_t)(t+256)*16, gh + t + 256);
        cp_commit();
    };

    load_chunk(0, 0);

    for (int ch = 0; ch < KCHUNKS; ch++){
        int cur = ch & 1;
        cp_wait0();
        __syncthreads();
        if (ch + 1 < KCHUNKS) load_chunk(ch + 1, cur ^ 1);

        const char* bStage = bPtr + (long)cur*8192;
        #pragma unroll
        for (int s = 0; s < 2; s++){
            uint32_t ah[2][4], al[2][4];
            #pragma unroll
            for (int mt2 = 0; mt2 < 2; mt2++){
                int mt = wm*2 + mt2;
                uint32_t aaddr = aBase + (uint32_t)(cur*NPA)*ABYTES
                               + (uint32_t)(mt*16 + rowl)*80 + (s*2 + ksel)*16;
                ldm_x4(ah[mt2], aaddr);
                if (NPA == 2) ldm_x4(al[mt2], aaddr + ABYTES);
            }
            #pragma unroll
            for (int nt = 0; nt < 4; nt++){
                int ntg = wn*4 + nt;
                uint2 bh = *(const uint2*)(bStage + ((s*16 + ntg)*32 + lane)*8);
                #pragma unroll
                for (int mt2 = 0; mt2 < 2; mt2++){
                    mma_f16(d[mt2][nt], ah[mt2], (const uint32_t*)&bh);
                    if (NPA == 2)
                        mma_f16(d[mt2][nt], al[mt2], (const uint32_t*)&bh);
                }
            }
        }
    }

    // epilogue
    int g = lane >> 2, t_ = lane & 3;
    #pragma unroll
    for (int mt2 = 0; mt2 < 2; mt2++){
        int rbase = m0 + wm*32 + mt2*16 + g;
        #pragma unroll
        for (int hf = 0; hf < 2; hf++){
            int row = rbase + hf*8;
            const float* pe = CONV ? (g_pe + (long)(row % LSEQ)*DMODEL) : (const float*)0;
            #pragma unroll
            for (int nt = 0; nt < 4; nt++){
                int col = wn*32 + nt*8 + t_*2;
                float v0 = d[mt2][nt][hf*2+0];
                float v1 = d[mt2][nt][hf*2+1];
                float2 bb = *(const float2*)(bias + col);
                v0 += bb.x; v1 += bb.y;
                if (CONV){
                    float2 p = *(const float2*)(pe + col);
                    v0 += p.x; v1 += p.y;
                }
                if (relu_flag){ v0 = fmaxf(v0, 0.f); v1 = fmaxf(v1, 0.f); }
                if (res_flag){
                    float2 r = *(const float2*)(res + (long)row*DMODEL + col);
                    v0 += r.x; v1 += r.y;
                }
                if (OUTF16){
                    uint32_t hh, ll;
                    split2(v0, v1, hh, ll);
                    long oi = (long)row*64 + (col >> 1);
                    Ch[oi] = hh; Cl[oi] = ll;
                } else {
                    *(float2*)(C + (long)row*DMODEL + col) = make_float2(v0, v1);
                }
            }
        }
    }
}

// ---------------- layernorm: one warp per row -> fp16 pair -------------------
__global__ void __launch_bounds__(256) ln_kernel(
    const float* __restrict__ x, const float* __restrict__ g,
    const float* __restrict__ b, uint32_t* __restrict__ yh,
    uint32_t* __restrict__ yl)
{
    int t = threadIdx.x;
    int row = blockIdx.x*8 + (t >> 5);
    int lane = t & 31;
    float4 v = ((const float4*)x)[row*32 + lane];
    float s  = v.x + v.y + v.z + v.w;
    float sq = v.x*v.x + v.y*v.y + v.z*v.z + v.w*v.w;
    #pragma unroll
    for (int o = 16; o; o >>= 1){
        s  += __shfl_xor_sync(0xffffffffu, s,  o);
        sq += __shfl_xor_sync(0xffffffffu, sq, o);
    }
    float mean = s * (1.f/DMODEL);
    float var  = sq * (1.f/DMODEL) - mean*mean;
    float rs = rsqrtf(var + 1e-5f);
    float4 gg = ((const float4*)g)[lane];
    float4 bb = ((const float4*)b)[lane];
    float o0 = (v.x-mean)*rs*gg.x + bb.x;
    float o1 = (v.y-mean)*rs*gg.y + bb.y;
    float o2 = (v.z-mean)*rs*gg.z + bb.z;
    float o3 = (v.w-mean)*rs*gg.w + bb.w;
    uint32_t h0,l0,h1,l1;
    split2(o0,o1,h0,l0); split2(o2,o3,h1,l1);
    ((uint2*)yh)[row*32 + lane] = make_uint2(h0,h1);
    ((uint2*)yl)[row*32 + lane] = make_uint2(l0,l1);
}

// ---------------- fused layernorm + depthwise conv k=7 -> fp16 pair ----------
__global__ void __launch_bounds__(256) lndw_kernel(
    const float* __restrict__ x, const float* __restrict__ g,
    const float* __restrict__ b, const float* __restrict__ wdw,
    const float* __restrict__ bdw, uint32_t* __restrict__ yh,
    uint32_t* __restrict__ yl)
{
    __shared__ float4 sln[56][32];
    int blk = blockIdx.x;
    int bidx = blk >> 3, lb = blk & 7;
    int l0 = lb * 50;
    int t = threadIdx.x, wid = t >> 5, lane = t & 31;

    float4 gg = ((const float4*)g)[lane];
    float4 bb = ((const float4*)b)[lane];

    #pragma unroll
    for (int rr = 0; rr < 7; rr++){
        int r = wid + rr*8;
        int l = l0 - 3 + r;
        float4 o4 = make_float4(0.f,0.f,0.f,0.f);
        if (l >= 0 && l < LSEQ){
            float4 v = ((const float4*)x)[(bidx*LSEQ + l)*32 + lane];
            float s  = v.x + v.y + v.z + v.w;
            float sq = v.x*v.x + v.y*v.y + v.z*v.z + v.w*v.w;
            #pragma unroll
            for (int o = 16; o; o >>= 1){
                s  += __shfl_xor_sync(0xffffffffu, s,  o);
                sq += __shfl_xor_sync(0xffffffffu, sq, o);
            }
            float mean = s * (1.f/DMODEL);
            float var  = sq * (1.f/DMODEL) - mean*mean;
            float rs = rsqrtf(var + 1e-5f);
            o4.x = (v.x-mean)*rs*gg.x + bb.x;
            o4.y = (v.y-mean)*rs*gg.y + bb.y;
            o4.z = (v.z-mean)*rs*gg.z + bb.z;
            o4.w = (v.w-mean)*rs*gg.w + bb.w;
        }
        sln[r][lane] = o4;
    }
    __syncthreads();

    float4 wv[7];
    #pragma unroll
    for (int tap = 0; tap < 7; tap++) wv[tap] = ((const float4*)wdw)[tap*32 + lane];
    float4 bias4 = ((const float4*)bdw)[lane];

    #pragma unroll
    for (int rr = 0; rr < 7; rr++){
        int r = wid + rr*8;
        if (r < 50){
            float4 acc = bias4;
            #pragma unroll
            for (int tap = 0; tap < 7; tap++){
                float4 xv = sln[r + tap][lane];
                acc.x += xv.x*wv[tap].x; acc.y += xv.y*wv[tap].y;
                acc.z += xv.z*wv[tap].z; acc.w += xv.w*wv[tap].w;
            }
            uint32_t h0,lo0,h1,lo1;
            split2(acc.x,acc.y,h0,lo0); split2(acc.z,acc.w,h1,lo1);
            long u2 = (long)(bidx*LSEQ + l0 + r)*32 + lane;
            ((uint2*)yh)[u2] = make_uint2(h0,h1);
            ((uint2*)yl)[u2] = make_uint2(lo0,lo1);
        }
    }
}

// ---------------- attention: single-pass, fp16-pair output -------------------
#define JT 100
__global__ void __launch_bounds__(416) attn_kernel(
    const float* __restrict__ Q, const float* __restrict__ K,
    const float* __restrict__ V, uint32_t* __restrict__ Oh,
    uint32_t* __restrict__ Ol)
{
    __shared__ float2 Ks[JT][8];
    __shared__ float2 Vs[JT][8];
    int bh = blockIdx.x;
    int b = bh >> 3, hd = bh & 7;
    int i = threadIdx.x;

    ull q2[8];
    if (i < LSEQ){
        const ull* qp = (const ull*)(Q + (b*LSEQ + i)*DMODEL + hd*HDIM);
        #pragma unroll
        for (int p = 0; p < 8; p++) q2[p] = qp[p];
    }
    float ssum = 0.f;
    ull o2[8];
    #pragma unroll
    for (int p = 0; p < 8; p++) o2[p] = 0ull;

    for (int jt = 0; jt < 4; jt++){
        __syncthreads();
        for (int idx = threadIdx.x; idx < JT*8; idx += 416){
            int jj = idx >> 3, hd2 = idx & 7;
            int gidx = (b*LSEQ + jt*JT + jj)*(DMODEL/2) + hd*8 + hd2;
            Ks[jj][hd2] = ((const float2*)K)[gidx];
            Vs[jj][hd2] = ((const float2*)V)[gidx];
        }
        __syncthreads();
        if (i < LSEQ){
            for (int jj = 0; jj < JT; jj++){
                ull acc = 0ull;
                const ull* kp = (const ull*)&Ks[jj][0];
                #pragma unroll
                for (int p = 0; p < 8; p++) ffma2(acc, q2[p], kp[p]);
                float2 af = *(float2*)&acc;
                float s = (af.x + af.y) * 0.25f;
                float pv = __expf(s);
                ssum += pv;
                ull p2 = pack2f(pv);
                const ull* vp = (const ull*)&Vs[jj][0];
                #pragma unroll
                for (int p = 0; p < 8; p++) ffma2(o2[p], p2, vp[p]);
            }
        }
    }
    if (i < LSEQ){
        float inv = 1.f / ssum;
        long obase = (long)(b*LSEQ + i)*64 + hd*8;
        #pragma unroll
        for (int p = 0; p < 8; p++){
            float2 f = *(float2*)&o2[p];
            uint32_t hh, ll;
            split2(f.x*inv, f.y*inv, hh, ll);
            Oh[obase + p] = hh;
            Ol[obase + p] = ll;
        }
    }
}

// ---------------- host orchestration ----------------------------------------
#define SMEM_CONV (2*64*80 + 2*8192)       // 26624 B
#define SMEM_GEMM (4*64*80 + 2*8192)       // 36864 B

extern "C" void kernel_launch(void* const* d_in, const int* in_sizes, int n_in,
                              void* d_out, int out_size)
{
    const float* x      = (const float*)d_in[0];
    const float* w_init = (const float*)d_in[1];
    const float* b_init = (const float*)d_in[2];
    const float* ln_cg  = (const float*)d_in[3];
    const float* ln_cb  = (const float*)d_in[4];
    const float* w_dw   = (const float*)d_in[5];
    const float* b_dw   = (const float*)d_in[6];
    const float* w_pw   = (const float*)d_in[7];
    const float* b_pw   = (const float*)d_in[8];
    const float* ln_ag  = (const float*)d_in[9];
    const float* ln_ab  = (const float*)d_in[10];
    const float* wq     = (const float*)d_in[11];
    const float* bq     = (const float*)d_in[12];
    const float* wk     = (const float*)d_in[13];
    const float* bk     = (const float*)d_in[14];
    const float* wv     = (const float*)d_in[15];
    const float* bv     = (const float*)d_in[16];
    const float* wo     = (const float*)d_in[17];
    const float* bo     = (const float*)d_in[18];
    const float* ln_fg  = (const float*)d_in[19];
    const float* ln_fb  = (const float*)d_in[20];
    const float* w1     = (const float*)d_in[21];
    const float* b1     = (const float*)d_in[22];
    const float* w2     = (const float*)d_in[23];
    const float* b2     = (const float*)d_in[24];

    __half *xph;
    float *h, *tmp, *q, *k, *v;
    uint32_t *lnh, *lnl, *dwh, *dwl, *ath, *atl, *ffh, *ffl, *bh;
    cudaGetSymbolAddress((void**)&xph, g_xph);
    cudaGetSymbolAddress((void**)&h,   g_h);
    cudaGetSymbolAddress((void**)&tmp, g_tmp);
    cudaGetSymbolAddress((void**)&q,   g_q);
    cudaGetSymbolAddress((void**)&k,   g_k);
    cudaGetSymbolAddress((void**)&v,   g_v);
    cudaGetSymbolAddress((void**)&lnh, g_lnh);
    cudaGetSymbolAddress((void**)&lnl, g_lnl);
    cudaGetSymbolAddress((void**)&dwh, g_dwh);
    cudaGetSymbolAddress((void**)&dwl, g_dwl);
    cudaGetSymbolAddress((void**)&ath, g_ath);
    cudaGetSymbolAddress((void**)&atl, g_atl);
    cudaGetSymbolAddress((void**)&ffh, g_ffh);
    cudaGetSymbolAddress((void**)&ffl, g_ffl);
    cudaGetSymbolAddress((void**)&bh,  g_bh);

    cudaFuncSetAttribute(gemm_mma<CONV_CHUNKS, true, 1, false>,
        cudaFuncAttributeMaxDynamicSharedMemorySize, SMEM_CONV);
    cudaFuncSetAttribute(gemm_mma<GEMM_CHUNKS, false, 2, false>,
        cudaFuncAttributeMaxDynamicSharedMemorySize, SMEM_GEMM);
    cudaFuncSetAttribute(gemm_mma<GEMM_CHUNKS, false, 2, true>,
        cudaFuncAttributeMaxDynamicSharedMemorySize, SMEM_GEMM);

    // 1) pad+split x, posenc, weight prep
    pad_kernel<<<(BATCH*LPAD*(CIN/4) + 255)/256, 256>>>(x);
    pe_kernel<<<(LSEQ*DMODEL + 255)/256, 256>>>();
    prep_w_kernel<<<(CONV_BWORDS + 10*GEMM_BWORDS)/256, 256>>>(
        w_init, w_pw, wq, wk, wv, wo, w1, w2);

    // 2) init conv (implicit GEMM, 1-pass fp16) + posenc -> h
    gemm_mma<CONV_CHUNKS, true, 1, false><<<MROWS/64, 256, SMEM_CONV>>>(
        xph, nullptr, bh, b_init, nullptr, h, nullptr, nullptr, 0, 0);

    #define GW(m) (bh + CONV_BWORDS + (m)*GEMM_BWORDS)

    // 3) 4x depthwise-separable conv blocks
    for (int i = 0; i < 4; i++){
        lndw_kernel<<<BATCH*8, 256>>>(h, ln_cg + i*DMODEL, ln_cb + i*DMODEL,
                                      w_dw + i*7*DMODEL, b_dw + i*DMODEL, dwh, dwl);
        gemm_mma<GEMM_CHUNKS, false, 2, false><<<MROWS/64, 256, SMEM_GEMM>>>(
            (const __half*)dwh, (const __half*)dwl, GW(i),
            b_pw + i*DMODEL, h, h, nullptr, nullptr, 1, 1);
    }

    // 4) attention
    ln_kernel<<<MROWS/8, 256>>>(h, ln_ag, ln_ab, lnh, lnl);
    gemm_mma<GEMM_CHUNKS, false, 2, false><<<MROWS/64, 256, SMEM_GEMM>>>(
        (const __half*)lnh, (const __half*)lnl, GW(4), bq, nullptr, q, nullptr, nullptr, 0, 0);
    gemm_mma<GEMM_CHUNKS, false, 2, false><<<MROWS/64, 256, SMEM_GEMM>>>(
        (const __half*)lnh, (const __half*)lnl, GW(5), bk, nullptr, k, nullptr, nullptr, 0, 0);
    gemm_mma<GEMM_CHUNKS, false, 2, false><<<MROWS/64, 256, SMEM_GEMM>>>(
        (const __half*)lnh, (const __half*)lnl, GW(6), bv, nullptr, v, nullptr, nullptr, 0, 0);
    attn_kernel<<<BATCH*NHEAD, 416>>>(q, k, v, ath, atl);
    gemm_mma<GEMM_CHUNKS, false, 2, false><<<MROWS/64, 256, SMEM_GEMM>>>(
        (const __half*)ath, (const __half*)atl, GW(7), bo, h, tmp, nullptr, nullptr, 0, 1);

    // 5) FFN -> d_out
    ln_kernel<<<MROWS/8, 256>>>(tmp, ln_fg, ln_fb, lnh, lnl);
    gemm_mma<GEMM_CHUNKS, false, 2, true><<<MROWS/64, 256, SMEM_GEMM>>>(
        (const __half*)lnh, (const __half*)lnl, GW(8), b1, nullptr, nullptr, ffh, ffl, 1, 0);
    gemm_mma<GEMM_CHUNKS, false, 2, false><<<MROWS/64, 256, SMEM_GEMM>>>(
        (const __half*)ffh, (const __half*)ffl, GW(9), b2, tmp, (float*)d_out, nullptr, nullptr, 0, 1);
}

// round 13
// speedup vs baseline: 3.6889x; 1.4687x over previous
#include <cuda_runtime.h>
#include <cuda_fp16.h>
#include <cstdint>

typedef unsigned long long ull;

// Problem constants
#define BATCH 64
#define LSEQ  400
#define CIN   500
#define DMODEL 128
#define NHEAD 8
#define HDIM  16
#define MROWS (BATCH*LSEQ)          // 25600
#define LPAD  (LSEQ+4)              // 404
#define KCONV 2500
#define CONV_CHUNKS 80              // K padded to 2560, BK=32
#define GEMM_CHUNKS 4               // K=128
#define CONV_BWORDS (CONV_CHUNKS*2048)
#define GEMM_BWORDS (GEMM_CHUNKS*2048)

// ---------------- scratch ----------------------------------------------------
__device__ __half g_xph[BATCH*LPAD*CIN + 4096];   // padded input, fp16 hi only
__device__ float g_pe[LSEQ*DMODEL];
__device__ float g_h  [MROWS*DMODEL];             // residual stream (fp32)
__device__ float g_tmp[MROWS*DMODEL];
// fp16-pair intermediates (half2-packed words, [MROWS][64])
__device__ uint32_t g_lnh[MROWS*64],  g_lnl[MROWS*64];
__device__ uint32_t g_dwh[MROWS*64],  g_dwl[MROWS*64];   // also K out at attn
__device__ uint32_t g_ath[MROWS*64],  g_atl[MROWS*64];
__device__ uint32_t g_ffh[MROWS*64],  g_ffl[MROWS*64];   // also Q out at attn
__device__ uint32_t g_vh [MROWS*64],  g_vl [MROWS*64];   // V out at attn

// pre-split weights in HMMA B-fragment order, fp16x2 words (hi plane only)
__device__ uint32_t g_bh[CONV_BWORDS + 10*GEMM_BWORDS];

// ---------------- helpers ----------------------------------------------------
__device__ __forceinline__ uint32_t smem_u32(const void* p){
    uint32_t a;
    asm("{ .reg .u64 t; cvta.to.shared.u64 t, %1; cvt.u32.u64 %0, t; }"
        : "=r"(a) : "l"(p));
    return a;
}
__device__ __forceinline__ void split2(float f0, float f1, uint32_t& h, uint32_t& l){
    __half h0 = __float2half_rn(f0);
    __half h1 = __float2half_rn(f1);
    float r0 = f0 - __half2float(h0);
    float r1 = f1 - __half2float(h1);
    __half l0 = __float2half_rn(r0);
    __half l1 = __float2half_rn(r1);
    unsigned short hu0 = *(unsigned short*)&h0, hu1 = *(unsigned short*)&h1;
    unsigned short lu0 = *(unsigned short*)&l0, lu1 = *(unsigned short*)&l1;
    h = (uint32_t)hu0 | ((uint32_t)hu1 << 16);
    l = (uint32_t)lu0 | ((uint32_t)lu1 << 16);
}
__device__ __forceinline__ uint32_t pack_hi2(float f0, float f1){
    __half h0 = __float2half_rn(f0);
    __half h1 = __float2half_rn(f1);
    unsigned short hu0 = *(unsigned short*)&h0, hu1 = *(unsigned short*)&h1;
    return (uint32_t)hu0 | ((uint32_t)hu1 << 16);
}
__device__ __forceinline__ void mma_f16(float* d, const uint32_t* a, const uint32_t* b){
    asm volatile(
        "mma.sync.aligned.m16n8k16.row.col.f32.f16.f16.f32 "
        "{%0,%1,%2,%3}, {%4,%5,%6,%7}, {%8,%9}, {%0,%1,%2,%3};"
        : "+f"(d[0]), "+f"(d[1]), "+f"(d[2]), "+f"(d[3])
        : "r"(a[0]), "r"(a[1]), "r"(a[2]), "r"(a[3]), "r"(b[0]), "r"(b[1]));
}
__device__ __forceinline__ void ldm_x4(uint32_t* r, uint32_t addr){
    asm volatile("ldmatrix.sync.aligned.m8n8.x4.shared.b16 {%0,%1,%2,%3}, [%4];"
        : "=r"(r[0]), "=r"(r[1]), "=r"(r[2]), "=r"(r[3]) : "r"(addr));
}
__device__ __forceinline__ void ldm_x2(uint32_t* r, uint32_t addr){
    asm volatile("ldmatrix.sync.aligned.m8n8.x2.shared.b16 {%0,%1}, [%2];"
        : "=r"(r[0]), "=r"(r[1]) : "r"(addr));
}
__device__ __forceinline__ void cp16(uint32_t daddr, const void* gptr){
    asm volatile("cp.async.cg.shared.global [%0], [%1], 16;"
                 :: "r"(daddr), "l"(gptr) : "memory");
}
__device__ __forceinline__ void cp8(uint32_t daddr, const void* gptr){
    asm volatile("cp.async.ca.shared.global [%0], [%1], 8;"
                 :: "r"(daddr), "l"(gptr) : "memory");
}
__device__ __forceinline__ void cp_commit(){
    asm volatile("cp.async.commit_group;" ::: "memory");
}
__device__ __forceinline__ void cp_wait0(){
    asm volatile("cp.async.wait_group 0;" ::: "memory");
}
__device__ __forceinline__ void cp_wait1(){
    asm volatile("cp.async.wait_group 1;" ::: "memory");
}

// ---------------- pad x -> fp16 hi plane [B,404,500] -------------------------
__global__ void __launch_bounds__(256) pad_kernel(const float* __restrict__ x){
    int idx = blockIdx.x*256 + threadIdx.x;
    if (idx >= BATCH*LPAD*(CIN/4)) return;
    int c4 = idx % (CIN/4);
    int rest = idx / (CIN/4);
    int lp = rest % LPAD;
    int b  = rest / LPAD;
    int l = lp - 2;
    float4 v = make_float4(0.f,0.f,0.f,0.f);
    if (l >= 0 && l < LSEQ) v = ((const float4*)x)[(b*LSEQ + l)*(CIN/4) + c4];
    uint32_t h0 = pack_hi2(v.x, v.y);
    uint32_t h1 = pack_hi2(v.z, v.w);
    long u2 = (long)rest*125 + c4;
    ((uint2*)g_xph)[u2] = make_uint2(h0, h1);
}

// ---------------- positional encoding table ---------------------------------
__global__ void __launch_bounds__(256) pe_kernel(){
    int idx = blockIdx.x*256 + threadIdx.x;
    if (idx >= LSEQ*DMODEL) return;
    int l = idx / DMODEL;
    int d = idx % DMODEL;
    int j = d & ~1;
    float div = expf(-(float)j * (logf(10000.f)/(float)DMODEL));
    float ang = (float)l * div;
    g_pe[idx] = (d & 1) ? cosf(ang) : sinf(ang);
}

// ---------------- weight prep into HMMA B-fragment order (fp16 hi) -----------
__global__ void __launch_bounds__(256) prep_w_kernel(
    const float* __restrict__ w_init, const float* __restrict__ w_pw,
    const float* __restrict__ wq, const float* __restrict__ wk,
    const float* __restrict__ wv, const float* __restrict__ wo,
    const float* __restrict__ w1, const float* __restrict__ w2)
{
    int flat = blockIdx.x*256 + threadIdx.x;
    const float* W; int K, ch, w2i;
    if (flat < CONV_BWORDS){
        W = w_init; K = KCONV;
        ch = flat >> 11; w2i = flat & 2047;
    } else {
        int rem = flat - CONV_BWORDS;
        int m = rem >> 13;
        int w2g = rem & 8191;
        ch = w2g >> 11; w2i = w2g & 2047;
        K = DMODEL;
        switch (m){
            case 0: case 1: case 2: case 3: W = w_pw + m*DMODEL*DMODEL; break;
            case 4: W = wq; break; case 5: W = wk; break;
            case 6: W = wv; break; case 7: W = wo; break;
            case 8: W = w1; break; default: W = w2; break;
        }
    }
    int j    = w2i & 1;
    int lane = (w2i >> 1) & 31;
    int snt  = w2i >> 6;
    int nt   = snt & 15;
    int s    = snt >> 4;
    int n  = nt*8 + (lane >> 2);
    int k2 = (lane & 3) + j*4 + s*8 + ch*16;
    int k  = 2*k2;
    float v0 = (k   < K) ? W[(long)k    *DMODEL + n] : 0.f;
    float v1 = (k+1 < K) ? W[(long)(k+1)*DMODEL + n] : 0.f;
    g_bh[flat] = pack_hi2(v0, v1);
}

// ---------------- 3-stage pipelined HMMA fp16 GEMM ---------------------------
// BM=64, 256 threads, B hi only.
// NPA=1 (conv): Ah*Bh.  NPA=2 (dense): Ah*Bh + Al*Bh.
template<int KCHUNKS, bool CONV, int NPA, bool OUTF16>
__global__ void __launch_bounds__(256) gemm_mma(
    const __half* __restrict__ Ah, const __half* __restrict__ Al,
    const uint32_t* __restrict__ Bhi,
    const float* __restrict__ bias, const float* __restrict__ res,
    float* __restrict__ C, uint32_t* __restrict__ Ch, uint32_t* __restrict__ Cl,
    int relu_flag, int res_flag)
{
    constexpr int ABYTES = 64*80;      // one plane, one stage (80B row stride)
    constexpr int AOFF_TOT = 3*NPA*ABYTES;

    extern __shared__ char smem[];
    uint32_t aBase = smem_u32(smem);
    uint32_t bBase = aBase + AOFF_TOT;
    char* bPtr = smem + AOFF_TOT;

    int t = threadIdx.x, lane = t & 31, wid = t >> 5;
    int m0 = blockIdx.x * 64;
    int wm = wid & 1, wn = wid >> 1;         // 2 x 4 warp grid

    int arow = t >> 2, aq = t & 3;
    long abase;
    if (CONV){
        int m = m0 + arow; int b = m / LSEQ; int l = m - b*LSEQ;
        abase = (long)(b*LPAD + l) * CIN;
    } else {
        abase = (long)(m0 + arow) * DMODEL;
    }
    uint32_t aDstRow = (uint32_t)arow*80 + (uint32_t)aq*16;

    float d[2][4][4];
    #pragma unroll
    for (int a=0;a<2;a++)
        #pragma unroll
        for (int b=0;b<4;b++)
            #pragma unroll
            for (int c=0;c<4;c++) d[a][b][c] = 0.f;

    int rowl = lane & 15, ksel = lane >> 4;

    auto load_chunk = [&](int ch, int stage){
        if (CONV){
            // 1000B row stride -> 8B alignment only: two cp8 per thread
            const char* gp = (const char*)(Ah + abase + ch*32 + aq*8);
            uint32_t dst = aBase + (uint32_t)(stage*NPA)*ABYTES + aDstRow;
            cp8(dst,     gp);
            cp8(dst + 8, gp + 8);
        } else {
            cp16(aBase + (uint32_t)(stage*NPA)*ABYTES + aDstRow,
                 Ah + abase + ch*32 + aq*8);
            if (NPA == 2)
                cp16(aBase + (uint32_t)(stage*NPA + 1)*ABYTES + aDstRow,
                     Al + abase + ch*32 + aq*8);
        }
        const uint4* gh = (const uint4*)(Bhi + (long)ch*2048);
        uint32_t dst = bBase + (uint32_t)stage*8192;
        cp16(dst + (uint32_t)t*16,       gh + t);
        cp16(dst + (uint32_t)(t+256)*16, gh + t + 256);
        cp_commit();
    };

    load_chunk(0, 0);
    if (KCHUNKS > 1) load_chunk(1, 1);

    int st = 0;
    for (int ch = 0; ch < KCHUNKS; ch++){
        if (ch + 1 < KCHUNKS) cp_wait1(); else cp_wait0();
        __syncthreads();
        if (ch + 2 < KCHUNKS){
            int s2 = st + 2; if (s2 >= 3) s2 -= 3;
            load_chunk(ch + 2, s2);
        }

        const char* bStage = bPtr + (long)st*8192;
        #pragma unroll
        for (int s = 0; s < 2; s++){
            uint32_t ah[2][4], al[2][4];
            #pragma unroll
            for (int mt2 = 0; mt2 < 2; mt2++){
                int mt = wm*2 + mt2;
                uint32_t aaddr = aBase + (uint32_t)(st*NPA)*ABYTES
                               + (uint32_t)(mt*16 + rowl)*80 + (s*2 + ksel)*16;
                ldm_x4(ah[mt2], aaddr);
                if (NPA == 2) ldm_x4(al[mt2], aaddr + ABYTES);
            }
            #pragma unroll
            for (int nt = 0; nt < 4; nt++){
                int ntg = wn*4 + nt;
                uint2 bh = *(const uint2*)(bStage + ((s*16 + ntg)*32 + lane)*8);
                #pragma unroll
                for (int mt2 = 0; mt2 < 2; mt2++){
                    mma_f16(d[mt2][nt], ah[mt2], (const uint32_t*)&bh);
                    if (NPA == 2)
                        mma_f16(d[mt2][nt], al[mt2], (const uint32_t*)&bh);
                }
            }
        }
        st = (st + 1 == 3) ? 0 : st + 1;
    }

    // epilogue
    int g = lane >> 2, t_ = lane & 3;
    #pragma unroll
    for (int mt2 = 0; mt2 < 2; mt2++){
        int rbase = m0 + wm*32 + mt2*16 + g;
        #pragma unroll
        for (int hf = 0; hf < 2; hf++){
            int row = rbase + hf*8;
            const float* pe = CONV ? (g_pe + (long)(row % LSEQ)*DMODEL) : (const float*)0;
            #pragma unroll
            for (int nt = 0; nt < 4; nt++){
                int col = wn*32 + nt*8 + t_*2;
                float v0 = d[mt2][nt][hf*2+0];
                float v1 = d[mt2][nt][hf*2+1];
                float2 bb = *(const float2*)(bias + col);
                v0 += bb.x; v1 += bb.y;
                if (CONV){
                    float2 p = *(const float2*)(pe + col);
                    v0 += p.x; v1 += p.y;
                }
                if (relu_flag){ v0 = fmaxf(v0, 0.f); v1 = fmaxf(v1, 0.f); }
                if (res_flag){
                    float2 r = *(const float2*)(res + (long)row*DMODEL + col);
                    v0 += r.x; v1 += r.y;
                }
                if (OUTF16){
                    uint32_t hh, ll;
                    split2(v0, v1, hh, ll);
                    long oi = (long)row*64 + (col >> 1);
                    Ch[oi] = hh; Cl[oi] = ll;
                } else {
                    *(float2*)(C + (long)row*DMODEL + col) = make_float2(v0, v1);
                }
            }
        }
    }
}

// ---------------- layernorm: one warp per row -> fp16 pair -------------------
__global__ void __launch_bounds__(256) ln_kernel(
    const float* __restrict__ x, const float* __restrict__ g,
    const float* __restrict__ b, uint32_t* __restrict__ yh,
    uint32_t* __restrict__ yl)
{
    int t = threadIdx.x;
    int row = blockIdx.x*8 + (t >> 5);
    int lane = t & 31;
    float4 v = ((const float4*)x)[row*32 + lane];
    float s  = v.x + v.y + v.z + v.w;
    float sq = v.x*v.x + v.y*v.y + v.z*v.z + v.w*v.w;
    #pragma unroll
    for (int o = 16; o; o >>= 1){
        s  += __shfl_xor_sync(0xffffffffu, s,  o);
        sq += __shfl_xor_sync(0xffffffffu, sq, o);
    }
    float mean = s * (1.f/DMODEL);
    float var  = sq * (1.f/DMODEL) - mean*mean;
    float rs = rsqrtf(var + 1e-5f);
    float4 gg = ((const float4*)g)[lane];
    float4 bb = ((const float4*)b)[lane];
    float o0 = (v.x-mean)*rs*gg.x + bb.x;
    float o1 = (v.y-mean)*rs*gg.y + bb.y;
    float o2 = (v.z-mean)*rs*gg.z + bb.z;
    float o3 = (v.w-mean)*rs*gg.w + bb.w;
    uint32_t h0,l0,h1,l1;
    split2(o0,o1,h0,l0); split2(o2,o3,h1,l1);
    ((uint2*)yh)[row*32 + lane] = make_uint2(h0,h1);
    ((uint2*)yl)[row*32 + lane] = make_uint2(l0,l1);
}

// ---------------- fused layernorm + depthwise conv k=7 -> fp16 pair ----------
__global__ void __launch_bounds__(256) lndw_kernel(
    const float* __restrict__ x, const float* __restrict__ g,
    const float* __restrict__ b, const float* __restrict__ wdw,
    const float* __restrict__ bdw, uint32_t* __restrict__ yh,
    uint32_t* __restrict__ yl)
{
    __shared__ float4 sln[56][32];
    int blk = blockIdx.x;
    int bidx = blk >> 3, lb = blk & 7;
    int l0 = lb * 50;
    int t = threadIdx.x, wid = t >> 5, lane = t & 31;

    float4 gg = ((const float4*)g)[lane];
    float4 bb = ((const float4*)b)[lane];

    #pragma unroll
    for (int rr = 0; rr < 7; rr++){
        int r = wid + rr*8;
        int l = l0 - 3 + r;
        float4 o4 = make_float4(0.f,0.f,0.f,0.f);
        if (l >= 0 && l < LSEQ){
            float4 v = ((const float4*)x)[(bidx*LSEQ + l)*32 + lane];
            float s  = v.x + v.y + v.z + v.w;
            float sq = v.x*v.x + v.y*v.y + v.z*v.z + v.w*v.w;
            #pragma unroll
            for (int o = 16; o; o >>= 1){
                s  += __shfl_xor_sync(0xffffffffu, s,  o);
                sq += __shfl_xor_sync(0xffffffffu, sq, o);
            }
            float mean = s * (1.f/DMODEL);
            float var  = sq * (1.f/DMODEL) - mean*mean;
            float rs = rsqrtf(var + 1e-5f);
            o4.x = (v.x-mean)*rs*gg.x + bb.x;
            o4.y = (v.y-mean)*rs*gg.y + bb.y;
            o4.z = (v.z-mean)*rs*gg.z + bb.z;
            o4.w = (v.w-mean)*rs*gg.w + bb.w;
        }
        sln[r][lane] = o4;
    }
    __syncthreads();

    float4 wv[7];
    #pragma unroll
    for (int tap = 0; tap < 7; tap++) wv[tap] = ((const float4*)wdw)[tap*32 + lane];
    float4 bias4 = ((const float4*)bdw)[lane];

    #pragma unroll
    for (int rr = 0; rr < 7; rr++){
        int r = wid + rr*8;
        if (r < 50){
            float4 acc = bias4;
            #pragma unroll
            for (int tap = 0; tap < 7; tap++){
                float4 xv = sln[r + tap][lane];
                acc.x += xv.x*wv[tap].x; acc.y += xv.y*wv[tap].y;
                acc.z += xv.z*wv[tap].z; acc.w += xv.w*wv[tap].w;
            }
            uint32_t h0,lo0,h1,lo1;
            split2(acc.x,acc.y,h0,lo0); split2(acc.z,acc.w,h1,lo1);
            long u2 = (long)(bidx*LSEQ + l0 + r)*32 + lane;
            ((uint2*)yh)[u2] = make_uint2(h0,h1);
            ((uint2*)yl)[u2] = make_uint2(lo0,lo1);
        }
    }
}

// ---------------- HMMA flash-attention ---------------------------------------
// One CTA per (b,h), 256 threads (8 warps). Q 2-pass (Qh+Ql vs Kh), P fp16,
// PV vs transposed V (Vt). No max-subtraction (scores bounded ~|2|).
// smem: Qh[400*48] Ql[400*48] Kh[400*48] Vt[16*816] Vstage[400*32]
#define SM_QH 0
#define SM_QL 19200
#define SM_KH 38400
#define SM_VT 57600
#define SM_VS (57600+13056)
#define SM_ATTN (SM_VS + 12800)      // 83456
__global__ void __launch_bounds__(256) attn_mma_kernel(
    const uint32_t* __restrict__ Qh, const uint32_t* __restrict__ Ql,
    const uint32_t* __restrict__ Kh, const uint32_t* __restrict__ Vh,
    uint32_t* __restrict__ Oh, uint32_t* __restrict__ Ol)
{
    extern __shared__ char sm[];
    uint32_t base = smem_u32(sm);
    uint32_t bQh = base + SM_QH, bQl = base + SM_QL;
    uint32_t bKh = base + SM_KH, bVt = base + SM_VT, bVs = base + SM_VS;

    int t = threadIdx.x, lane = t & 31, wid = t >> 5;
    int bh = blockIdx.x;
    int b = bh >> 3, hd = bh & 7;
    long rowbase = (long)(b*LSEQ)*64 + hd*8;   // word offset of row l's head slice

    // stage Q/K/V head slices (32B per row each)
    for (int i = t; i < 800; i += 256){
        int r = i >> 1, half = i & 1;
        long gw = rowbase + (long)r*64 + half*4;
        uint32_t doff = (uint32_t)r*48 + half*16;
        cp16(bQh + doff, Qh + gw);
        cp16(bQl + doff, Ql + gw);
        cp16(bKh + doff, Kh + gw);
        cp16(bVs + (uint32_t)r*32 + half*16, Vh + gw);
    }
    cp_commit(); cp_wait0();
    __syncthreads();

    // transpose V: Vs[r][d] -> Vt[d][r]  (Vt rows 816B stride, conflict-free)
    for (int i = t; i < 3200; i += 256){
        int r = i >> 3, w8 = i & 7;
        uint32_t val = *(uint32_t*)(sm + SM_VS + r*32 + w8*4);
        __half lo = *(__half*)&val;
        __half hi = *((__half*)&val + 1);
        *(__half*)(sm + SM_VT + (2*w8  )*816 + r*2) = lo;
        *(__half*)(sm + SM_VT + (2*w8+1)*816 + r*2) = hi;
    }
    __syncthreads();

    int rowl = lane & 15, ksel = lane >> 4;
    int l8 = lane & 7, lh = (lane >> 3) & 1;
    int g = lane >> 2, t_ = lane & 3;

    for (int qt = wid; qt < 25; qt += 8){
        uint32_t aqh[4], aql[4];
        uint32_t qoff = (uint32_t)(qt*16 + rowl)*48 + ksel*16;
        ldm_x4(aqh, bQh + qoff);
        ldm_x4(aql, bQl + qoff);

        float o0[4] = {0,0,0,0}, o1[4] = {0,0,0,0};
        float rs0 = 0.f, rs1 = 0.f;

        for (int jb = 0; jb < 25; jb++){
            // two n8 score tiles (j = jb*16 + tile*8)
            float s0[4] = {0,0,0,0}, s1[4] = {0,0,0,0};
            uint32_t bk[2];
            ldm_x2(bk, bKh + (uint32_t)(jb*16 + l8)*48 + lh*16);
            mma_f16(s0, aqh, bk);
            mma_f16(s0, aql, bk);
            ldm_x2(bk, bKh + (uint32_t)(jb*16 + 8 + l8)*48 + lh*16);
            mma_f16(s1, aqh, bk);
            mma_f16(s1, aql, bk);

            float e00 = __expf(s0[0]*0.25f), e01 = __expf(s0[1]*0.25f);
            float e02 = __expf(s0[2]*0.25f), e03 = __expf(s0[3]*0.25f);
            float e10 = __expf(s1[0]*0.25f), e11 = __expf(s1[1]*0.25f);
            float e12 = __expf(s1[2]*0.25f), e13 = __expf(s1[3]*0.25f);
            rs0 += e00 + e01 + e10 + e11;
            rs1 += e02 + e03 + e12 + e13;

            uint32_t pa[4];
            pa[0] = pack_hi2(e00, e01);
            pa[1] = pack_hi2(e02, e03);
            pa[2] = pack_hi2(e10, e11);
            pa[3] = pack_hi2(e12, e13);

            uint32_t bv[2];
            ldm_x2(bv, bVt + (uint32_t)l8*816 + (uint32_t)jb*32 + lh*16);
            mma_f16(o0, pa, bv);
            ldm_x2(bv, bVt + (uint32_t)(8 + l8)*816 + (uint32_t)jb*32 + lh*16);
            mma_f16(o1, pa, bv);
        }

        // reduce row sums across the quad (lanes sharing row g)
        rs0 += __shfl_xor_sync(0xffffffffu, rs0, 1);
        rs0 += __shfl_xor_sync(0xffffffffu, rs0, 2);
        rs1 += __shfl_xor_sync(0xffffffffu, rs1, 1);
        rs1 += __shfl_xor_sync(0xffffffffu, rs1, 2);
        float i0 = 1.f / rs0, i1 = 1.f / rs1;

        long base0 = rowbase + (long)(qt*16 + g)*64;
        long base1 = base0 + 8*64;
        uint32_t hh, ll;
        split2(o0[0]*i0, o0[1]*i0, hh, ll); Oh[base0 + t_]   = hh; Ol[base0 + t_]   = ll;
        split2(o1[0]*i0, o1[1]*i0, hh, ll); Oh[base0 + 4+t_] = hh; Ol[base0 + 4+t_] = ll;
        split2(o0[2]*i1, o0[3]*i1, hh, ll); Oh[base1 + t_]   = hh; Ol[base1 + t_]   = ll;
        split2(o1[2]*i1, o1[3]*i1, hh, ll); Oh[base1 + 4+t_] = hh; Ol[base1 + 4+t_] = ll;
    }
}

// ---------------- host orchestration ----------------------------------------
#define SMEM_CONV (3*64*80 + 3*8192)       // 39936 B
#define SMEM_GEMM (3*2*64*80 + 3*8192)     // 55296 B

extern "C" void kernel_launch(void* const* d_in, const int* in_sizes, int n_in,
                              void* d_out, int out_size)
{
    const float* x      = (const float*)d_in[0];
    const float* w_init = (const float*)d_in[1];
    const float* b_init = (const float*)d_in[2];
    const float* ln_cg  = (const float*)d_in[3];
    const float* ln_cb  = (const float*)d_in[4];
    const float* w_dw   = (const float*)d_in[5];
    const float* b_dw   = (const float*)d_in[6];
    const float* w_pw   = (const float*)d_in[7];
    const float* b_pw   = (const float*)d_in[8];
    const float* ln_ag  = (const float*)d_in[9];
    const float* ln_ab  = (const float*)d_in[10];
    const float* wq     = (const float*)d_in[11];
    const float* bq     = (const float*)d_in[12];
    const float* wk     = (const float*)d_in[13];
    const float* bk     = (const float*)d_in[14];
    const float* wv     = (const float*)d_in[15];
    const float* bv     = (const float*)d_in[16];
    const float* wo     = (const float*)d_in[17];
    const float* bo     = (const float*)d_in[18];
    const float* ln_fg  = (const float*)d_in[19];
    const float* ln_fb  = (const float*)d_in[20];
    const float* w1     = (const float*)d_in[21];
    const float* b1     = (const float*)d_in[22];
    const float* w2     = (const float*)d_in[23];
    const float* b2     = (const float*)d_in[24];

    __half *xph;
    float *h, *tmp;
    uint32_t *lnh, *lnl, *dwh, *dwl, *ath, *atl, *ffh, *ffl, *vh, *vl, *bh;
    cudaGetSymbolAddress((void**)&xph, g_xph);
    cudaGetSymbolAddress((void**)&h,   g_h);
    cudaGetSymbolAddress((void**)&tmp, g_tmp);
    cudaGetSymbolAddress((void**)&lnh, g_lnh);
    cudaGetSymbolAddress((void**)&lnl, g_lnl);
    cudaGetSymbolAddress((void**)&dwh, g_dwh);
    cudaGetSymbolAddress((void**)&dwl, g_dwl);
    cudaGetSymbolAddress((void**)&ath, g_ath);
    cudaGetSymbolAddress((void**)&atl, g_atl);
    cudaGetSymbolAddress((void**)&ffh, g_ffh);
    cudaGetSymbolAddress((void**)&ffl, g_ffl);
    cudaGetSymbolAddress((void**)&vh,  g_vh);
    cudaGetSymbolAddress((void**)&vl,  g_vl);
    cudaGetSymbolAddress((void**)&bh,  g_bh);

    cudaFuncSetAttribute(gemm_mma<CONV_CHUNKS, true, 1, false>,
        cudaFuncAttributeMaxDynamicSharedMemorySize, SMEM_CONV);
    cudaFuncSetAttribute(gemm_mma<GEMM_CHUNKS, false, 2, false>,
        cudaFuncAttributeMaxDynamicSharedMemorySize, SMEM_GEMM);
    cudaFuncSetAttribute(gemm_mma<GEMM_CHUNKS, false, 2, true>,
        cudaFuncAttributeMaxDynamicSharedMemorySize, SMEM_GEMM);
    cudaFuncSetAttribute(attn_mma_kernel,
        cudaFuncAttributeMaxDynamicSharedMemorySize, SM_ATTN);

    // 1) pad+split x, posenc, weight prep
    pad_kernel<<<(BATCH*LPAD*(CIN/4) + 255)/256, 256>>>(x);
    pe_kernel<<<(LSEQ*DMODEL + 255)/256, 256>>>();
    prep_w_kernel<<<(CONV_BWORDS + 10*GEMM_BWORDS)/256, 256>>>(
        w_init, w_pw, wq, wk, wv, wo, w1, w2);

    // 2) init conv (implicit GEMM, 1-pass fp16) + posenc -> h
    gemm_mma<CONV_CHUNKS, true, 1, false><<<MROWS/64, 256, SMEM_CONV>>>(
        xph, nullptr, bh, b_init, nullptr, h, nullptr, nullptr, 0, 0);

    #define GW(m) (bh + CONV_BWORDS + (m)*GEMM_BWORDS)

    // 3) 4x depthwise-separable conv blocks
    for (int i = 0; i < 4; i++){
        lndw_kernel<<<BATCH*8, 256>>>(h, ln_cg + i*DMODEL, ln_cb + i*DMODEL,
                                      w_dw + i*7*DMODEL, b_dw + i*DMODEL, dwh, dwl);
        gemm_mma<GEMM_CHUNKS, false, 2, false><<<MROWS/64, 256, SMEM_GEMM>>>(
            (const __half*)dwh, (const __half*)dwl, GW(i),
            b_pw + i*DMODEL, h, h, nullptr, nullptr, 1, 1);
    }

    // 4) attention (QKV emitted as fp16 pairs; attention all-HMMA)
    ln_kernel<<<MROWS/8, 256>>>(h, ln_ag, ln_ab, lnh, lnl);
    gemm_mma<GEMM_CHUNKS, false, 2, true><<<MROWS/64, 256, SMEM_GEMM>>>(
        (const __half*)lnh, (const __half*)lnl, GW(4), bq, nullptr, nullptr, ffh, ffl, 0, 0);
    gemm_mma<GEMM_CHUNKS, false, 2, true><<<MROWS/64, 256, SMEM_GEMM>>>(
        (const __half*)lnh, (const __half*)lnl, GW(5), bk, nullptr, nullptr, dwh, dwl, 0, 0);
    gemm_mma<GEMM_CHUNKS, false, 2, true><<<MROWS/64, 256, SMEM_GEMM>>>(
        (const __half*)lnh, (const __half*)lnl, GW(6), bv, nullptr, nullptr, vh, vl, 0, 0);
    attn_mma_kernel<<<BATCH*NHEAD, 256, SM_ATTN>>>(ffh, ffl, dwh, vh, ath, atl);
    gemm_mma<GEMM_CHUNKS, false, 2, false><<<MROWS/64, 256, SMEM_GEMM>>>(
        (const __half*)ath, (const __half*)atl, GW(7), bo, h, tmp, nullptr, nullptr, 0, 1);

    // 5) FFN -> d_out
    ln_kernel<<<MROWS/8, 256>>>(tmp, ln_fg, ln_fb, lnh, lnl);
    gemm_mma<GEMM_CHUNKS, false, 2, true><<<MROWS/64, 256, SMEM_GEMM>>>(
        (const __half*)lnh, (const __half*)lnl, GW(8), b1, nullptr, nullptr, ffh, ffl, 1, 0);
    gemm_mma<GEMM_CHUNKS, false, 2, false><<<MROWS/64, 256, SMEM_GEMM>>>(
        (const __half*)ffh, (const __half*)ffl, GW(9), b2, tmp, (float*)d_out, nullptr, nullptr, 0, 1);
}